// round 1
// baseline (speedup 1.0000x reference)
#include <cuda_runtime.h>
#include <math.h>

#define DIMC 384
#define NH 6
#define HD 64
#define MLPD 1536
#define BATCH 8
#define SEQ 1024
#define ROWS (BATCH*SEQ)   /* 8192 */
#define BH (BATCH*NH)      /* 48 */
#define QKVW (3*DIMC)      /* 1152 */

// ---------------- scratch (static device globals; no allocation) ----------------
__device__ float g_h[ROWS*DIMC];        // LN output (reused for LN1 and LN2)
__device__ float g_qkv[ROWS*QKVW];      // QKV gemm output [8192][1152]
__device__ float g_qt[BH*HD*SEQ];       // Q transposed [bh][d][n], pre-scaled
__device__ float g_kt[BH*HD*SEQ];       // K transposed [bh][d][n]
__device__ float g_attn[ROWS*DIMC];     // attention out in [B,N,C] layout
__device__ float g_mlp[ROWS*MLPD];      // MLP hidden

// ---------------- LayerNorm: one block per row of 384 ----------------
__global__ __launch_bounds__(128) void ln_kernel(const float* __restrict__ x,
                                                 const float* __restrict__ w,
                                                 const float* __restrict__ b,
                                                 float* __restrict__ out)
{
    int row = blockIdx.x;
    const float* xr = x + (size_t)row * DIMC;
    float* orow = out + (size_t)row * DIMC;
    int t = threadIdx.x;
    float v0 = xr[t], v1 = xr[t + 128], v2 = xr[t + 256];
    __shared__ float red[128];
    red[t] = v0 + v1 + v2;
    __syncthreads();
    #pragma unroll
    for (int o = 64; o > 0; o >>= 1) {
        if (t < o) red[t] += red[t + o];
        __syncthreads();
    }
    float mean = red[0] * (1.0f / DIMC);
    __syncthreads();
    float d0 = v0 - mean, d1 = v1 - mean, d2 = v2 - mean;
    red[t] = d0 * d0 + d1 * d1 + d2 * d2;
    __syncthreads();
    #pragma unroll
    for (int o = 64; o > 0; o >>= 1) {
        if (t < o) red[t] += red[t + o];
        __syncthreads();
    }
    float var = red[0] * (1.0f / DIMC);
    float r = rsqrtf(var + 1e-5f);
    orow[t]       = d0 * r * w[t]       + b[t];
    orow[t + 128] = d1 * r * w[t + 128] + b[t + 128];
    orow[t + 256] = d2 * r * w[t + 256] + b[t + 256];
}

// ---------------- generic SGEMM: C[M,N] = A[M,K] @ W[N,K]^T (+epilogue) -------
// EPI 0: none    EPI 1: + bias + res    EPI 2: + bias then exact GELU
template<int EPI>
__global__ __launch_bounds__(256) void sgemm_nt(const float* __restrict__ A,
                                                const float* __restrict__ W,
                                                const float* __restrict__ bias,
                                                const float* res,
                                                float* C,
                                                int M, int N, int K)
{
    const int BK = 8;
    __shared__ float As[BK][132];
    __shared__ float Bs[BK][132];
    int tid = threadIdx.x;
    int tx = tid & 15, ty = tid >> 4;
    int m0 = blockIdx.y * 128, n0 = blockIdx.x * 128;

    float acc[8][8];
    #pragma unroll
    for (int i = 0; i < 8; i++)
        #pragma unroll
        for (int j = 0; j < 8; j++) acc[i][j] = 0.f;

    int lrow = tid >> 1;
    int lkk = (tid & 1) * 4;
    const float* Ap = A + (size_t)(m0 + lrow) * K + lkk;
    const float* Wp = W + (size_t)(n0 + lrow) * K + lkk;

    for (int k0 = 0; k0 < K; k0 += BK) {
        float4 av = *(const float4*)(Ap + k0);
        float4 bv = *(const float4*)(Wp + k0);
        As[lkk + 0][lrow] = av.x; As[lkk + 1][lrow] = av.y;
        As[lkk + 2][lrow] = av.z; As[lkk + 3][lrow] = av.w;
        Bs[lkk + 0][lrow] = bv.x; Bs[lkk + 1][lrow] = bv.y;
        Bs[lkk + 2][lrow] = bv.z; Bs[lkk + 3][lrow] = bv.w;
        __syncthreads();
        #pragma unroll
        for (int k = 0; k < BK; k++) {
            float a[8], b[8];
            *(float4*)(a)     = *(float4*)&As[k][ty * 4];
            *(float4*)(a + 4) = *(float4*)&As[k][ty * 4 + 64];
            *(float4*)(b)     = *(float4*)&Bs[k][tx * 4];
            *(float4*)(b + 4) = *(float4*)&Bs[k][tx * 4 + 64];
            #pragma unroll
            for (int i = 0; i < 8; i++)
                #pragma unroll
                for (int j = 0; j < 8; j++)
                    acc[i][j] = fmaf(a[i], b[j], acc[i][j]);
        }
        __syncthreads();
    }

    #pragma unroll
    for (int i = 0; i < 8; i++) {
        int r = m0 + ((i < 4) ? (ty * 4 + i) : (64 + ty * 4 + i - 4));
        #pragma unroll
        for (int jh = 0; jh < 2; jh++) {
            int c = n0 + tx * 4 + jh * 64;
            float v[4];
            #pragma unroll
            for (int j = 0; j < 4; j++) v[j] = acc[i][jh * 4 + j];
            if (EPI == 1 || EPI == 2) {
                float4 bb = *(const float4*)(bias + c);
                v[0] += bb.x; v[1] += bb.y; v[2] += bb.z; v[3] += bb.w;
            }
            if (EPI == 1) {
                float4 rr = *(const float4*)(res + (size_t)r * N + c);
                v[0] += rr.x; v[1] += rr.y; v[2] += rr.z; v[3] += rr.w;
            }
            if (EPI == 2) {
                #pragma unroll
                for (int j = 0; j < 4; j++)
                    v[j] = 0.5f * v[j] * (1.0f + erff(v[j] * 0.7071067811865476f));
            }
            float4 ov; ov.x = v[0]; ov.y = v[1]; ov.z = v[2]; ov.w = v[3];
            *(float4*)(C + (size_t)r * N + c) = ov;
        }
    }
}

// ---------------- Q/K transpose to [bh][d][n]; scale folded into Q ----------
__global__ __launch_bounds__(256) void transpose_qk(const float* __restrict__ qkv,
                                                    float* __restrict__ qt,
                                                    float* __restrict__ kt)
{
    __shared__ float Ts[64 * 65];
    int bh = blockIdx.y;
    int b = bh / NH, h = bh % NH;
    int n0 = blockIdx.x * 64;
    int tid = threadIdx.x;

    #pragma unroll
    for (int pass = 0; pass < 2; pass++) {
        int off = (pass == 0) ? (h * HD) : (DIMC + h * HD);
        float scl = (pass == 0) ? 0.125f : 1.0f;   // D^-0.5 = 1/8
        float* dst = (pass == 0) ? qt : kt;
        #pragma unroll
        for (int p = 0; p < 4; p++) {
            int i = tid + p * 256;
            int n = i >> 4, d4 = (i & 15) * 4;
            float4 v = *(const float4*)(qkv + (size_t)(b * SEQ + n0 + n) * QKVW + off + d4);
            Ts[(d4 + 0) * 65 + n] = v.x * scl;
            Ts[(d4 + 1) * 65 + n] = v.y * scl;
            Ts[(d4 + 2) * 65 + n] = v.z * scl;
            Ts[(d4 + 3) * 65 + n] = v.w * scl;
        }
        __syncthreads();
        #pragma unroll
        for (int p = 0; p < 4; p++) {
            int i = tid + p * 256;
            int d = i >> 4, n4 = (i & 15) * 4;
            float4 v;
            v.x = Ts[d * 65 + n4 + 0];
            v.y = Ts[d * 65 + n4 + 1];
            v.z = Ts[d * 65 + n4 + 2];
            v.w = Ts[d * 65 + n4 + 3];
            *(float4*)(dst + (size_t)(bh * HD + d) * SEQ + n0 + n4) = v;
        }
        __syncthreads();
    }
}

// ---------------- fused L2Q attention: per (bh, 64-query tile) ---------------
// sum-normalized ReLU(alpha*s^2 + beta*s + gamma); no softmax max needed, so a
// single pass accumulating O_unnorm and rowsum suffices.
__global__ __launch_bounds__(256) void attn_kernel(const float* __restrict__ qt,
                                                   const float* __restrict__ kt,
                                                   const float* __restrict__ qkv,
                                                   const float* __restrict__ alpha,
                                                   const float* __restrict__ beta,
                                                   const float* __restrict__ gamma,
                                                   float* __restrict__ out)
{
    extern __shared__ float sm[];
    float* Qs = sm;                // [64][64] : Qs[d][r]
    float* Ks = Qs + 4096;         // [64][64] : Ks[d][c]
    float* Vs = Ks + 4096;         // [64][64] : Vs[c][v]
    float* Ss = Vs + 4096;         // [64][68] : Ss[r][c]
    float* red = Ss + 64 * 68;     // [64] row sums

    int bh = blockIdx.y;
    int b = bh / NH, h = bh % NH;
    int r0 = blockIdx.x * 64;
    int tid = threadIdx.x;
    int tx = tid & 15, ty = tid >> 4;
    float al = alpha[h], be = beta[h], ga = gamma[h];

    if (tid < 64) red[tid] = 0.f;

    const float* qbase = qt + (size_t)bh * HD * SEQ + r0;
    #pragma unroll
    for (int p = 0; p < 4; p++) {
        int i = tid + p * 256;
        int d = i >> 4, c4 = (i & 15) * 4;
        *(float4*)&Qs[d * 64 + c4] = *(const float4*)(qbase + (size_t)d * SEQ + c4);
    }

    float o[4][4];
    #pragma unroll
    for (int i = 0; i < 4; i++)
        #pragma unroll
        for (int j = 0; j < 4; j++) o[i][j] = 0.f;
    float rs[4] = {0.f, 0.f, 0.f, 0.f};

    const float* kbase = kt + (size_t)bh * HD * SEQ;

    for (int c0 = 0; c0 < SEQ; c0 += 64) {
        __syncthreads();   // protects Ks/Vs reuse + Q tile visibility + red zero
        #pragma unroll
        for (int p = 0; p < 4; p++) {
            int i = tid + p * 256;
            int d = i >> 4, c4 = (i & 15) * 4;
            *(float4*)&Ks[d * 64 + c4] = *(const float4*)(kbase + (size_t)d * SEQ + c0 + c4);
        }
        #pragma unroll
        for (int p = 0; p < 4; p++) {
            int i = tid + p * 256;
            int c = i >> 4, v4 = (i & 15) * 4;
            *(float4*)&Vs[c * 64 + v4] =
                *(const float4*)(qkv + (size_t)(b * SEQ + c0 + c) * QKVW + 2 * DIMC + h * HD + v4);
        }
        __syncthreads();

        // S = Q @ K^T (scale pre-folded into Q)
        float s[4][4];
        #pragma unroll
        for (int i = 0; i < 4; i++)
            #pragma unroll
            for (int j = 0; j < 4; j++) s[i][j] = 0.f;
        #pragma unroll 16
        for (int d = 0; d < 64; d++) {
            float a[4], bb[4];
            *(float4*)a  = *(float4*)&Qs[d * 64 + ty * 4];
            *(float4*)bb = *(float4*)&Ks[d * 64 + tx * 4];
            #pragma unroll
            for (int i = 0; i < 4; i++)
                #pragma unroll
                for (int j = 0; j < 4; j++)
                    s[i][j] = fmaf(a[i], bb[j], s[i][j]);
        }
        // activation + rowsum partials + stage into Ss
        #pragma unroll
        for (int i = 0; i < 4; i++) {
            #pragma unroll
            for (int j = 0; j < 4; j++) {
                float xv = s[i][j];
                float f = fmaf(al * xv, xv, fmaf(be, xv, ga));
                f = fmaxf(f, 0.f);
                s[i][j] = f;
                rs[i] += f;
            }
            float4 v; v.x = s[i][0]; v.y = s[i][1]; v.z = s[i][2]; v.w = s[i][3];
            *(float4*)&Ss[(ty * 4 + i) * 68 + tx * 4] = v;
        }
        __syncthreads();

        // O += f(S) @ V
        #pragma unroll 16
        for (int c = 0; c < 64; c++) {
            float a[4];
            #pragma unroll
            for (int i = 0; i < 4; i++) a[i] = Ss[(ty * 4 + i) * 68 + c];
            float4 bv = *(float4*)&Vs[c * 64 + tx * 4];
            #pragma unroll
            for (int i = 0; i < 4; i++) {
                o[i][0] = fmaf(a[i], bv.x, o[i][0]);
                o[i][1] = fmaf(a[i], bv.y, o[i][1]);
                o[i][2] = fmaf(a[i], bv.z, o[i][2]);
                o[i][3] = fmaf(a[i], bv.w, o[i][3]);
            }
        }
    }

    __syncthreads();
    #pragma unroll
    for (int i = 0; i < 4; i++) atomicAdd(&red[ty * 4 + i], rs[i]);
    __syncthreads();

    #pragma unroll
    for (int i = 0; i < 4; i++) {
        float inv = 1.0f / (red[ty * 4 + i] + 1e-6f);
        float4 v;
        v.x = o[i][0] * inv; v.y = o[i][1] * inv;
        v.z = o[i][2] * inv; v.w = o[i][3] * inv;
        *(float4*)(out + (size_t)(b * SEQ + r0 + ty * 4 + i) * DIMC + h * HD + tx * 4) = v;
    }
}

// ---------------- launch ------------------------------------------------------
extern "C" void kernel_launch(void* const* d_in, const int* in_sizes, int n_in,
                              void* d_out, int out_size)
{
    const float* x      = (const float*)d_in[0];
    const float* qkv_w  = (const float*)d_in[1];
    const float* proj_w = (const float*)d_in[2];
    const float* proj_b = (const float*)d_in[3];
    const float* alpha  = (const float*)d_in[4];
    const float* beta   = (const float*)d_in[5];
    const float* gamma  = (const float*)d_in[6];
    const float* ln1_w  = (const float*)d_in[7];
    const float* ln1_b  = (const float*)d_in[8];
    const float* ln2_w  = (const float*)d_in[9];
    const float* ln2_b  = (const float*)d_in[10];
    const float* w1     = (const float*)d_in[11];
    const float* b1     = (const float*)d_in[12];
    const float* w2     = (const float*)d_in[13];
    const float* b2     = (const float*)d_in[14];
    float* out = (float*)d_out;

    float *h, *qkv, *qt, *ktp, *attn, *mlp;
    cudaGetSymbolAddress((void**)&h,    g_h);
    cudaGetSymbolAddress((void**)&qkv,  g_qkv);
    cudaGetSymbolAddress((void**)&qt,   g_qt);
    cudaGetSymbolAddress((void**)&ktp,  g_kt);
    cudaGetSymbolAddress((void**)&attn, g_attn);
    cudaGetSymbolAddress((void**)&mlp,  g_mlp);

    const int attn_smem = (3 * 4096 + 64 * 68 + 64) * 4;  // 66816 B
    cudaFuncSetAttribute(attn_kernel, cudaFuncAttributeMaxDynamicSharedMemorySize, attn_smem);

    // 1) LN1
    ln_kernel<<<ROWS, 128>>>(x, ln1_w, ln1_b, h);
    // 2) QKV gemm: [8192,384] x [1152,384]^T
    sgemm_nt<0><<<dim3(QKVW / 128, ROWS / 128), 256>>>(h, qkv_w, nullptr, nullptr, qkv,
                                                       ROWS, QKVW, DIMC);
    // 3) transpose Q,K to [bh][d][n] (scale folded into Q)
    transpose_qk<<<dim3(SEQ / 64, BH), 256>>>(qkv, qt, ktp);
    // 4) fused attention
    attn_kernel<<<dim3(SEQ / 64, BH), 256, attn_smem>>>(qt, ktp, qkv,
                                                        alpha, beta, gamma, attn);
    // 5) proj + bias + residual(x)  -> x1 stored in d_out
    sgemm_nt<1><<<dim3(DIMC / 128, ROWS / 128), 256>>>(attn, proj_w, proj_b, x, out,
                                                       ROWS, DIMC, DIMC);
    // 6) LN2 on x1
    ln_kernel<<<ROWS, 128>>>(out, ln2_w, ln2_b, h);
    // 7) MLP1 + bias + exact GELU
    sgemm_nt<2><<<dim3(MLPD / 128, ROWS / 128), 256>>>(h, w1, b1, nullptr, mlp,
                                                       ROWS, MLPD, DIMC);
    // 8) MLP2 + bias + residual(x1)  -> final output
    sgemm_nt<1><<<dim3(DIMC / 128, ROWS / 128), 256>>>(mlp, w2, b2, out, out,
                                                       ROWS, DIMC, MLPD);
}

// round 5
// speedup vs baseline: 1.5361x; 1.5361x over previous
#include <cuda_runtime.h>
#include <cuda_bf16.h>
#include <math.h>
#include <stdint.h>

#define DIMC 384
#define NH 6
#define HD 64
#define MLPD 1536
#define BATCH 8
#define SEQ 1024
#define ROWS (BATCH*SEQ)   /* 8192 */
#define BH (BATCH*NH)      /* 48 */
#define QKVW (3*DIMC)      /* 1152 */

// ---------------- scratch ----------------
__device__ float g_h[ROWS*DIMC];        // LN output
__device__ float g_qkv[ROWS*QKVW];      // QKV gemm output
__device__ float g_qt[BH*HD*SEQ];       // Q^T [bh][d][n], pre-scaled
__device__ float g_kt[BH*HD*SEQ];       // K^T [bh][d][n]
__device__ float g_attn[ROWS*DIMC];     // attention out [B,N,C]
__device__ float g_mlp[ROWS*MLPD];      // MLP hidden

__device__ __forceinline__ uint32_t smem_u32(const void* p) {
    uint32_t a;
    asm("{ .reg .u64 t; cvta.to.shared.u64 t, %1; cvt.u32.u64 %0, t; }" : "=r"(a) : "l"(p));
    return a;
}

__device__ __forceinline__ void ldm_x4(uint32_t* r, uint32_t addr) {
    asm volatile("ldmatrix.sync.aligned.m8n8.x4.shared.b16 {%0,%1,%2,%3}, [%4];"
                 : "=r"(r[0]), "=r"(r[1]), "=r"(r[2]), "=r"(r[3]) : "r"(addr));
}

__device__ __forceinline__ void mma_bf16(float* d, const uint32_t* a, const uint32_t* b) {
    asm volatile("mma.sync.aligned.m16n8k16.row.col.f32.bf16.bf16.f32 "
                 "{%0,%1,%2,%3}, {%4,%5,%6,%7}, {%8,%9}, {%0,%1,%2,%3};"
                 : "+f"(d[0]), "+f"(d[1]), "+f"(d[2]), "+f"(d[3])
                 : "r"(a[0]), "r"(a[1]), "r"(a[2]), "r"(a[3]), "r"(b[0]), "r"(b[1]));
}

__device__ __forceinline__ void split_bf16(float x, uint16_t& hi, uint16_t& lo) {
    __nv_bfloat16 h = __float2bfloat16(x);
    __nv_bfloat16 l = __float2bfloat16(x - __bfloat162float(h));
    hi = __bfloat16_as_ushort(h);
    lo = __bfloat16_as_ushort(l);
}

// ================= mma.sync bf16x3 GEMM ==========================
// C[M,N] = A[M,K] @ W[N,K]^T,  acc += Ah*Wh + Ah*Wl + Al*Wh in fp32.
// Block: 256 threads (8 warps, 2x4), tile 128x128, K-chunk = 32 (bf16).
// Smem per operand tile: 128 rows x 40 bf16 (80B padded) = 10240 B.
// EPI 0: none   EPI 1: +bias +res   EPI 2: +bias, exact GELU
#define LDS_ROW 80          /* bytes per padded row */
#define TBUF 10240          /* bytes per tile buffer */
#define OFF_AH 0
#define OFF_AL 10240
#define OFF_WH 20480
#define OFF_WL 30720

template<int EPI>
__global__ __launch_bounds__(256) void mma_gemm(const float* __restrict__ A,
                                                const float* __restrict__ W,
                                                const float* __restrict__ bias,
                                                const float* __restrict__ res,
                                                float* __restrict__ C,
                                                int M, int N, int K)
{
    __shared__ __align__(128) char smem[40960];
    uint32_t sbase = smem_u32(smem);

    int tid = threadIdx.x;
    int wid = tid >> 5;
    uint32_t lane = tid & 31;
    int wm = wid >> 2;          // 0..1   (64 M-rows each)
    int wn = wid & 3;           // 0..3   (32 N-cols each)
    int n0 = blockIdx.x * 128, m0 = blockIdx.y * 128;

    float acc[4][4][4];
    #pragma unroll
    for (int i = 0; i < 4; i++)
        #pragma unroll
        for (int j = 0; j < 4; j++)
            #pragma unroll
            for (int q = 0; q < 4; q++) acc[i][j][q] = 0.f;

    // ldmatrix lane addresses (byte offsets inside a tile buffer)
    // A (row-major m16k16): lane l -> row (l%16), k-half (l/16)*16B
    uint32_t aOff = (uint32_t)(wm * 64 + (lane & 15)) * LDS_ROW + (lane >> 4) * 16;
    // B (W row-major n8k16 pairs): lane l -> n row (l%8)+(l/16)*8, k-half ((l/8)%2)*16B
    uint32_t bOff = (uint32_t)(wn * 32 + (lane & 7) + ((lane >> 4) << 3)) * LDS_ROW
                    + ((lane >> 3) & 1) * 16;

    int nchunks = K >> 5;
    const float* Ap = A + (size_t)m0 * K;
    const float* Wp = W + (size_t)n0 * K;

    for (int c = 0; c < nchunks; c++) {
        int k0 = c << 5;
        __syncthreads();
        // ---- load fp32, split to bf16 hi/lo, stage to smem ----
        #pragma unroll
        for (int p = 0; p < 4; p++) {
            int idx = tid + p * 256;          // 0..1023
            int r = idx >> 3, cc = (idx & 7) * 4;
            uint32_t so = (uint32_t)r * LDS_ROW + cc * 2;

            float4 va = *(const float4*)(Ap + (size_t)r * K + k0 + cc);
            uint16_t h0,l0,h1,l1,h2,l2,h3,l3;
            split_bf16(va.x, h0, l0); split_bf16(va.y, h1, l1);
            split_bf16(va.z, h2, l2); split_bf16(va.w, h3, l3);
            uint2 v;
            v.x = (uint32_t)h0 | ((uint32_t)h1 << 16);
            v.y = (uint32_t)h2 | ((uint32_t)h3 << 16);
            *(uint2*)(smem + OFF_AH + so) = v;
            v.x = (uint32_t)l0 | ((uint32_t)l1 << 16);
            v.y = (uint32_t)l2 | ((uint32_t)l3 << 16);
            *(uint2*)(smem + OFF_AL + so) = v;

            float4 vw = *(const float4*)(Wp + (size_t)r * K + k0 + cc);
            split_bf16(vw.x, h0, l0); split_bf16(vw.y, h1, l1);
            split_bf16(vw.z, h2, l2); split_bf16(vw.w, h3, l3);
            v.x = (uint32_t)h0 | ((uint32_t)h1 << 16);
            v.y = (uint32_t)h2 | ((uint32_t)h3 << 16);
            *(uint2*)(smem + OFF_WH + so) = v;
            v.x = (uint32_t)l0 | ((uint32_t)l1 << 16);
            v.y = (uint32_t)l2 | ((uint32_t)l3 << 16);
            *(uint2*)(smem + OFF_WL + so) = v;
        }
        __syncthreads();

        // ---- compute: 2 k16 steps ----
        #pragma unroll
        for (int ks = 0; ks < 2; ks++) {
            uint32_t ko = ks * 32;            // 16 bf16 = 32 bytes
            uint32_t ah[4][4], al[4][4], wh[2][4], wl[2][4];
            #pragma unroll
            for (int mi = 0; mi < 4; mi++) {
                uint32_t ad = sbase + aOff + mi * (16 * LDS_ROW) + ko;
                ldm_x4(ah[mi], ad + OFF_AH);
                ldm_x4(al[mi], ad + OFF_AL);
            }
            #pragma unroll
            for (int j = 0; j < 2; j++) {
                uint32_t bd = sbase + bOff + j * (16 * LDS_ROW) + ko;
                ldm_x4(wh[j], bd + OFF_WH);
                ldm_x4(wl[j], bd + OFF_WL);
            }
            #pragma unroll
            for (int mi = 0; mi < 4; mi++) {
                #pragma unroll
                for (int nj = 0; nj < 4; nj++) {
                    const uint32_t* bh = &wh[nj >> 1][(nj & 1) * 2];
                    const uint32_t* bl = &wl[nj >> 1][(nj & 1) * 2];
                    mma_bf16(acc[mi][nj], ah[mi], bh);
                    mma_bf16(acc[mi][nj], ah[mi], bl);
                    mma_bf16(acc[mi][nj], al[mi], bh);
                }
            }
        }
    }

    // ---- epilogue ----
    #pragma unroll
    for (int mi = 0; mi < 4; mi++) {
        int r0 = m0 + wm * 64 + mi * 16 + (lane >> 2);
        #pragma unroll
        for (int nj = 0; nj < 4; nj++) {
            int col = n0 + wn * 32 + nj * 8 + (lane & 3) * 2;
            float v[4];
            v[0] = acc[mi][nj][0]; v[1] = acc[mi][nj][1];
            v[2] = acc[mi][nj][2]; v[3] = acc[mi][nj][3];
            if (EPI == 1 || EPI == 2) {
                float2 bb = *(const float2*)(bias + col);
                v[0] += bb.x; v[1] += bb.y; v[2] += bb.x; v[3] += bb.y;
            }
            if (EPI == 1) {
                float2 ra = *(const float2*)(res + (size_t)r0 * N + col);
                float2 rb = *(const float2*)(res + (size_t)(r0 + 8) * N + col);
                v[0] += ra.x; v[1] += ra.y; v[2] += rb.x; v[3] += rb.y;
            }
            if (EPI == 2) {
                #pragma unroll
                for (int q = 0; q < 4; q++)
                    v[q] = 0.5f * v[q] * (1.0f + erff(v[q] * 0.7071067811865476f));
            }
            float2 o0; o0.x = v[0]; o0.y = v[1];
            float2 o1; o1.x = v[2]; o1.y = v[3];
            *(float2*)(C + (size_t)r0 * N + col) = o0;
            *(float2*)(C + (size_t)(r0 + 8) * N + col) = o1;
        }
    }
}

// ---------------- LayerNorm ----------------
__global__ __launch_bounds__(128) void ln_kernel(const float* __restrict__ x,
                                                 const float* __restrict__ w,
                                                 const float* __restrict__ b,
                                                 float* __restrict__ out)
{
    int row = blockIdx.x;
    const float* xr = x + (size_t)row * DIMC;
    float* orow = out + (size_t)row * DIMC;
    int t = threadIdx.x;
    float v0 = xr[t], v1 = xr[t + 128], v2 = xr[t + 256];
    __shared__ float red[128];
    red[t] = v0 + v1 + v2;
    __syncthreads();
    #pragma unroll
    for (int o = 64; o > 0; o >>= 1) {
        if (t < o) red[t] += red[t + o];
        __syncthreads();
    }
    float mean = red[0] * (1.0f / DIMC);
    __syncthreads();
    float d0 = v0 - mean, d1 = v1 - mean, d2 = v2 - mean;
    red[t] = d0 * d0 + d1 * d1 + d2 * d2;
    __syncthreads();
    #pragma unroll
    for (int o = 64; o > 0; o >>= 1) {
        if (t < o) red[t] += red[t + o];
        __syncthreads();
    }
    float var = red[0] * (1.0f / DIMC);
    float r = rsqrtf(var + 1e-5f);
    orow[t]       = d0 * r * w[t]       + b[t];
    orow[t + 128] = d1 * r * w[t + 128] + b[t + 128];
    orow[t + 256] = d2 * r * w[t + 256] + b[t + 256];
}

// ---------------- Q/K transpose to [bh][d][n]; scale folded into Q ----------
__global__ __launch_bounds__(256) void transpose_qk(const float* __restrict__ qkv,
                                                    float* __restrict__ qt,
                                                    float* __restrict__ kt)
{
    __shared__ float Ts[64 * 65];
    int bh = blockIdx.y;
    int b = bh / NH, h = bh % NH;
    int n0 = blockIdx.x * 64;
    int tid = threadIdx.x;

    #pragma unroll
    for (int pass = 0; pass < 2; pass++) {
        int off = (pass == 0) ? (h * HD) : (DIMC + h * HD);
        float scl = (pass == 0) ? 0.125f : 1.0f;
        float* dst = (pass == 0) ? qt : kt;
        #pragma unroll
        for (int p = 0; p < 4; p++) {
            int i = tid + p * 256;
            int n = i >> 4, d4 = (i & 15) * 4;
            float4 v = *(const float4*)(qkv + (size_t)(b * SEQ + n0 + n) * QKVW + off + d4);
            Ts[(d4 + 0) * 65 + n] = v.x * scl;
            Ts[(d4 + 1) * 65 + n] = v.y * scl;
            Ts[(d4 + 2) * 65 + n] = v.z * scl;
            Ts[(d4 + 3) * 65 + n] = v.w * scl;
        }
        __syncthreads();
        #pragma unroll
        for (int p = 0; p < 4; p++) {
            int i = tid + p * 256;
            int d = i >> 4, n4 = (i & 15) * 4;
            float4 v;
            v.x = Ts[d * 65 + n4 + 0];
            v.y = Ts[d * 65 + n4 + 1];
            v.z = Ts[d * 65 + n4 + 2];
            v.w = Ts[d * 65 + n4 + 3];
            *(float4*)(dst + (size_t)(bh * HD + d) * SEQ + n0 + n4) = v;
        }
        __syncthreads();
    }
}

// ---------------- fused L2Q attention (fp32) ---------------------------------
__global__ __launch_bounds__(256) void attn_kernel(const float* __restrict__ qt,
                                                   const float* __restrict__ kt,
                                                   const float* __restrict__ qkv,
                                                   const float* __restrict__ alpha,
                                                   const float* __restrict__ beta,
                                                   const float* __restrict__ gamma,
                                                   float* __restrict__ out)
{
    extern __shared__ float sm[];
    float* Qs = sm;
    float* Ks = Qs + 4096;
    float* Vs = Ks + 4096;
    float* Ss = Vs + 4096;
    float* red = Ss + 64 * 68;

    int bh = blockIdx.y;
    int b = bh / NH, h = bh % NH;
    int r0 = blockIdx.x * 64;
    int tid = threadIdx.x;
    int tx = tid & 15, ty = tid >> 4;
    float al = alpha[h], be = beta[h], ga = gamma[h];

    if (tid < 64) red[tid] = 0.f;

    const float* qbase = qt + (size_t)bh * HD * SEQ + r0;
    #pragma unroll
    for (int p = 0; p < 4; p++) {
        int i = tid + p * 256;
        int d = i >> 4, c4 = (i & 15) * 4;
        *(float4*)&Qs[d * 64 + c4] = *(const float4*)(qbase + (size_t)d * SEQ + c4);
    }

    float o[4][4];
    #pragma unroll
    for (int i = 0; i < 4; i++)
        #pragma unroll
        for (int j = 0; j < 4; j++) o[i][j] = 0.f;
    float rs[4] = {0.f, 0.f, 0.f, 0.f};

    const float* kbase = kt + (size_t)bh * HD * SEQ;

    for (int c0 = 0; c0 < SEQ; c0 += 64) {
        __syncthreads();
        #pragma unroll
        for (int p = 0; p < 4; p++) {
            int i = tid + p * 256;
            int d = i >> 4, c4 = (i & 15) * 4;
            *(float4*)&Ks[d * 64 + c4] = *(const float4*)(kbase + (size_t)d * SEQ + c0 + c4);
        }
        #pragma unroll
        for (int p = 0; p < 4; p++) {
            int i = tid + p * 256;
            int c = i >> 4, v4 = (i & 15) * 4;
            *(float4*)&Vs[c * 64 + v4] =
                *(const float4*)(qkv + (size_t)(b * SEQ + c0 + c) * QKVW + 2 * DIMC + h * HD + v4);
        }
        __syncthreads();

        float s[4][4];
        #pragma unroll
        for (int i = 0; i < 4; i++)
            #pragma unroll
            for (int j = 0; j < 4; j++) s[i][j] = 0.f;
        #pragma unroll 16
        for (int d = 0; d < 64; d++) {
            float a[4], bb[4];
            *(float4*)a  = *(float4*)&Qs[d * 64 + ty * 4];
            *(float4*)bb = *(float4*)&Ks[d * 64 + tx * 4];
            #pragma unroll
            for (int i = 0; i < 4; i++)
                #pragma unroll
                for (int j = 0; j < 4; j++)
                    s[i][j] = fmaf(a[i], bb[j], s[i][j]);
        }
        #pragma unroll
        for (int i = 0; i < 4; i++) {
            #pragma unroll
            for (int j = 0; j < 4; j++) {
                float xv = s[i][j];
                float f = fmaf(al * xv, xv, fmaf(be, xv, ga));
                f = fmaxf(f, 0.f);
                s[i][j] = f;
                rs[i] += f;
            }
            float4 v; v.x = s[i][0]; v.y = s[i][1]; v.z = s[i][2]; v.w = s[i][3];
            *(float4*)&Ss[(ty * 4 + i) * 68 + tx * 4] = v;
        }
        __syncthreads();

        #pragma unroll 16
        for (int c = 0; c < 64; c++) {
            float a[4];
            #pragma unroll
            for (int i = 0; i < 4; i++) a[i] = Ss[(ty * 4 + i) * 68 + c];
            float4 bv = *(float4*)&Vs[c * 64 + tx * 4];
            #pragma unroll
            for (int i = 0; i < 4; i++) {
                o[i][0] = fmaf(a[i], bv.x, o[i][0]);
                o[i][1] = fmaf(a[i], bv.y, o[i][1]);
                o[i][2] = fmaf(a[i], bv.z, o[i][2]);
                o[i][3] = fmaf(a[i], bv.w, o[i][3]);
            }
        }
    }

    __syncthreads();
    #pragma unroll
    for (int i = 0; i < 4; i++) atomicAdd(&red[ty * 4 + i], rs[i]);
    __syncthreads();

    #pragma unroll
    for (int i = 0; i < 4; i++) {
        float inv = 1.0f / (red[ty * 4 + i] + 1e-6f);
        float4 v;
        v.x = o[i][0] * inv; v.y = o[i][1] * inv;
        v.z = o[i][2] * inv; v.w = o[i][3] * inv;
        *(float4*)(out + (size_t)(b * SEQ + r0 + ty * 4 + i) * DIMC + h * HD + tx * 4) = v;
    }
}

// ---------------- launch ------------------------------------------------------
extern "C" void kernel_launch(void* const* d_in, const int* in_sizes, int n_in,
                              void* d_out, int out_size)
{
    const float* x      = (const float*)d_in[0];
    const float* qkv_w  = (const float*)d_in[1];
    const float* proj_w = (const float*)d_in[2];
    const float* proj_b = (const float*)d_in[3];
    const float* alpha  = (const float*)d_in[4];
    const float* beta   = (const float*)d_in[5];
    const float* gamma  = (const float*)d_in[6];
    const float* ln1_w  = (const float*)d_in[7];
    const float* ln1_b  = (const float*)d_in[8];
    const float* ln2_w  = (const float*)d_in[9];
    const float* ln2_b  = (const float*)d_in[10];
    const float* w1     = (const float*)d_in[11];
    const float* b1     = (const float*)d_in[12];
    const float* w2     = (const float*)d_in[13];
    const float* b2     = (const float*)d_in[14];
    float* out = (float*)d_out;

    float *h, *qkv, *qt, *ktp, *attn, *mlp;
    cudaGetSymbolAddress((void**)&h,    g_h);
    cudaGetSymbolAddress((void**)&qkv,  g_qkv);
    cudaGetSymbolAddress((void**)&qt,   g_qt);
    cudaGetSymbolAddress((void**)&ktp,  g_kt);
    cudaGetSymbolAddress((void**)&attn, g_attn);
    cudaGetSymbolAddress((void**)&mlp,  g_mlp);

    const int attn_smem = (3 * 4096 + 64 * 68 + 64) * 4;
    cudaFuncSetAttribute(attn_kernel, cudaFuncAttributeMaxDynamicSharedMemorySize, attn_smem);

    // 1) LN1
    ln_kernel<<<ROWS, 128>>>(x, ln1_w, ln1_b, h);
    // 2) QKV gemm: [8192,384] @ [1152,384]^T
    mma_gemm<0><<<dim3(QKVW / 128, ROWS / 128), 256>>>(h, qkv_w, nullptr, nullptr, qkv,
                                                       ROWS, QKVW, DIMC);
    // 3) transpose Q,K
    transpose_qk<<<dim3(SEQ / 64, BH), 256>>>(qkv, qt, ktp);
    // 4) fused attention
    attn_kernel<<<dim3(SEQ / 64, BH), 256, attn_smem>>>(qt, ktp, qkv,
                                                        alpha, beta, gamma, attn);
    // 5) proj + bias + residual(x) -> out
    mma_gemm<1><<<dim3(DIMC / 128, ROWS / 128), 256>>>(attn, proj_w, proj_b, x, out,
                                                       ROWS, DIMC, DIMC);
    // 6) LN2
    ln_kernel<<<ROWS, 128>>>(out, ln2_w, ln2_b, h);
    // 7) MLP1 + bias + exact GELU
    mma_gemm<2><<<dim3(MLPD / 128, ROWS / 128), 256>>>(h, w1, b1, nullptr, mlp,
                                                       ROWS, MLPD, DIMC);
    // 8) MLP2 + bias + residual(out)
    mma_gemm<1><<<dim3(DIMC / 128, ROWS / 128), 256>>>(mlp, w2, b2, out, out,
                                                       ROWS, DIMC, MLPD);
}

// round 6
// speedup vs baseline: 2.2245x; 1.4481x over previous
#include <cuda_runtime.h>
#include <cuda_bf16.h>
#include <math.h>
#include <stdint.h>

#define DIMC 384
#define NH 6
#define HD 64
#define MLPD 1536
#define BATCH 8
#define SEQ 1024
#define ROWS (BATCH*SEQ)   /* 8192 */
#define BH (BATCH*NH)      /* 48 */
#define QKVW (3*DIMC)      /* 1152 */

typedef unsigned short u16;

// ---------------- scratch (bf16 hi/lo pairs) ----------------
__device__ u16 g_h_hi[ROWS*DIMC],   g_h_lo[ROWS*DIMC];      // LN out
__device__ u16 g_qkv_hi[ROWS*QKVW], g_qkv_lo[ROWS*QKVW];    // QKV out
__device__ u16 g_at_hi[ROWS*DIMC],  g_at_lo[ROWS*DIMC];     // attn out
__device__ u16 g_mlp_hi[ROWS*MLPD], g_mlp_lo[ROWS*MLPD];    // MLP hidden
__device__ u16 g_qw_hi[QKVW*DIMC],  g_qw_lo[QKVW*DIMC];
__device__ u16 g_pw_hi[DIMC*DIMC],  g_pw_lo[DIMC*DIMC];
__device__ u16 g_w1_hi[MLPD*DIMC],  g_w1_lo[MLPD*DIMC];
__device__ u16 g_w2_hi[DIMC*MLPD],  g_w2_lo[DIMC*MLPD];

__device__ __forceinline__ uint32_t smem_u32(const void* p) {
    uint32_t a;
    asm("{ .reg .u64 t; cvta.to.shared.u64 t, %1; cvt.u32.u64 %0, t; }" : "=r"(a) : "l"(p));
    return a;
}
__device__ __forceinline__ void ldm_x4(uint32_t* r, uint32_t addr) {
    asm volatile("ldmatrix.sync.aligned.m8n8.x4.shared.b16 {%0,%1,%2,%3}, [%4];"
                 : "=r"(r[0]), "=r"(r[1]), "=r"(r[2]), "=r"(r[3]) : "r"(addr));
}
__device__ __forceinline__ void ldm_x4_t(uint32_t* r, uint32_t addr) {
    asm volatile("ldmatrix.sync.aligned.m8n8.x4.trans.shared.b16 {%0,%1,%2,%3}, [%4];"
                 : "=r"(r[0]), "=r"(r[1]), "=r"(r[2]), "=r"(r[3]) : "r"(addr));
}
__device__ __forceinline__ void mma_bf16(float* d, const uint32_t* a, const uint32_t* b) {
    asm volatile("mma.sync.aligned.m16n8k16.row.col.f32.bf16.bf16.f32 "
                 "{%0,%1,%2,%3}, {%4,%5,%6,%7}, {%8,%9}, {%0,%1,%2,%3};"
                 : "+f"(d[0]), "+f"(d[1]), "+f"(d[2]), "+f"(d[3])
                 : "r"(a[0]), "r"(a[1]), "r"(a[2]), "r"(a[3]), "r"(b[0]), "r"(b[1]));
}
__device__ __forceinline__ uint32_t pack_hi2(float x, float y) {
    __nv_bfloat162 t = __floats2bfloat162_rn(x, y);
    return *(uint32_t*)&t;
}
__device__ __forceinline__ float bf_hi(float x) {
    return __bfloat162float(__float2bfloat16(x));
}

// ---------------- weight split: fp32 -> bf16 hi/lo ----------------
__global__ __launch_bounds__(256) void split_kernel(const float* __restrict__ in,
                                                    u16* __restrict__ hi,
                                                    u16* __restrict__ lo)
{
    int idx = (blockIdx.x * 256 + threadIdx.x) * 4;
    float4 v = *(const float4*)(in + idx);
    float h0 = bf_hi(v.x), h1 = bf_hi(v.y), h2 = bf_hi(v.z), h3 = bf_hi(v.w);
    uint2 a, b;
    a.x = pack_hi2(h0, h1); a.y = pack_hi2(h2, h3);
    b.x = pack_hi2(v.x - h0, v.y - h1); b.y = pack_hi2(v.z - h2, v.w - h3);
    *(uint2*)(hi + idx) = a;
    *(uint2*)(lo + idx) = b;
}

// ---------------- LayerNorm -> bf16 hi/lo ----------------
__global__ __launch_bounds__(128) void ln_kernel(const float* __restrict__ x,
                                                 const float* __restrict__ w,
                                                 const float* __restrict__ b,
                                                 u16* __restrict__ ohi,
                                                 u16* __restrict__ olo)
{
    int row = blockIdx.x;
    const float* xr = x + (size_t)row * DIMC;
    int t = threadIdx.x;
    float v0 = xr[t], v1 = xr[t + 128], v2 = xr[t + 256];
    __shared__ float red[128];
    red[t] = v0 + v1 + v2;
    __syncthreads();
    #pragma unroll
    for (int o = 64; o > 0; o >>= 1) {
        if (t < o) red[t] += red[t + o];
        __syncthreads();
    }
    float mean = red[0] * (1.0f / DIMC);
    __syncthreads();
    float d0 = v0 - mean, d1 = v1 - mean, d2 = v2 - mean;
    red[t] = d0 * d0 + d1 * d1 + d2 * d2;
    __syncthreads();
    #pragma unroll
    for (int o = 64; o > 0; o >>= 1) {
        if (t < o) red[t] += red[t + o];
        __syncthreads();
    }
    float var = red[0] * (1.0f / DIMC);
    float r = rsqrtf(var + 1e-5f);
    size_t base = (size_t)row * DIMC;
    #pragma unroll
    for (int p = 0; p < 3; p++) {
        int i = t + p * 128;
        float d = (p == 0 ? d0 : p == 1 ? d1 : d2);
        float y = d * r * w[i] + b[i];
        float h = bf_hi(y);
        ohi[base + i] = __bfloat16_as_ushort(__float2bfloat16(h));
        olo[base + i] = __bfloat16_as_ushort(__float2bfloat16(y - h));
    }
}

// ================= mma.sync bf16x3 GEMM (pre-split operands) =================
// C[M,N] = A[M,K] @ W[N,K]^T,  acc += Ah*Wh + Ah*Wl + Al*Wh in fp32.
// 256 threads (8 warps 2x4), tile 128x128, K-chunk 32.
// EPI 0: split-store bf16 hi/lo   EPI 1: +bias +res -> fp32   EPI 2: +bias, GELU, split-store
#define LDS_ROW 80
#define OFF_AH 0
#define OFF_AL 10240
#define OFF_WH 20480
#define OFF_WL 30720

template<int EPI>
__global__ __launch_bounds__(256) void mma_gemm(const u16* __restrict__ Ah_,
                                                const u16* __restrict__ Al_,
                                                const u16* __restrict__ Wh_,
                                                const u16* __restrict__ Wl_,
                                                const float* __restrict__ bias,
                                                const float* __restrict__ res,
                                                float* __restrict__ C,
                                                u16* __restrict__ Chi,
                                                u16* __restrict__ Clo,
                                                int M, int N, int K)
{
    __shared__ __align__(128) char smem[40960];
    uint32_t sbase = smem_u32(smem);

    int tid = threadIdx.x;
    int wid = tid >> 5;
    uint32_t lane = tid & 31;
    int wm = wid >> 2, wn = wid & 3;
    int n0 = blockIdx.x * 128, m0 = blockIdx.y * 128;

    float acc[4][4][4];
    #pragma unroll
    for (int i = 0; i < 4; i++)
        #pragma unroll
        for (int j = 0; j < 4; j++)
            #pragma unroll
            for (int q = 0; q < 4; q++) acc[i][j][q] = 0.f;

    uint32_t aOff = (uint32_t)(wm * 64 + (lane & 15)) * LDS_ROW + (lane >> 4) * 16;
    uint32_t bOff = (uint32_t)(wn * 32 + (lane & 7) + ((lane >> 4) << 3)) * LDS_ROW
                    + ((lane >> 3) & 1) * 16;

    const u16* s0 = Ah_ + (size_t)m0 * K;
    const u16* s1 = Al_ + (size_t)m0 * K;
    const u16* s2 = Wh_ + (size_t)n0 * K;
    const u16* s3 = Wl_ + (size_t)n0 * K;

    int nchunks = K >> 5;
    uint4 pf[8];
    // prefetch chunk 0
    #pragma unroll
    for (int p = 0; p < 8; p++) {
        int t = p >> 1;
        int i = tid + (p & 1) * 256;
        int r = i >> 2, q = i & 3;
        const u16* src = (t == 0) ? s0 : (t == 1) ? s1 : (t == 2) ? s2 : s3;
        pf[p] = *(const uint4*)(src + (size_t)r * K + q * 8);
    }

    for (int c = 0; c < nchunks; c++) {
        __syncthreads();
        #pragma unroll
        for (int p = 0; p < 8; p++) {
            int t = p >> 1;
            int i = tid + (p & 1) * 256;
            int r = i >> 2, q = i & 3;
            *(uint4*)(smem + t * 10240 + r * LDS_ROW + q * 16) = pf[p];
        }
        __syncthreads();
        if (c + 1 < nchunks) {
            int k0 = (c + 1) << 5;
            #pragma unroll
            for (int p = 0; p < 8; p++) {
                int t = p >> 1;
                int i = tid + (p & 1) * 256;
                int r = i >> 2, q = i & 3;
                const u16* src = (t == 0) ? s0 : (t == 1) ? s1 : (t == 2) ? s2 : s3;
                pf[p] = *(const uint4*)(src + (size_t)r * K + k0 + q * 8);
            }
        }
        #pragma unroll
        for (int ks = 0; ks < 2; ks++) {
            uint32_t ko = ks * 32;
            uint32_t ah[4][4], al[4][4], wh[2][4], wl[2][4];
            #pragma unroll
            for (int mi = 0; mi < 4; mi++) {
                uint32_t ad = sbase + aOff + mi * (16 * LDS_ROW) + ko;
                ldm_x4(ah[mi], ad + OFF_AH);
                ldm_x4(al[mi], ad + OFF_AL);
            }
            #pragma unroll
            for (int j = 0; j < 2; j++) {
                uint32_t bd = sbase + bOff + j * (16 * LDS_ROW) + ko;
                ldm_x4(wh[j], bd + OFF_WH);
                ldm_x4(wl[j], bd + OFF_WL);
            }
            #pragma unroll
            for (int mi = 0; mi < 4; mi++) {
                #pragma unroll
                for (int nj = 0; nj < 4; nj++) {
                    const uint32_t* bh = &wh[nj >> 1][(nj & 1) * 2];
                    const uint32_t* bl = &wl[nj >> 1][(nj & 1) * 2];
                    mma_bf16(acc[mi][nj], ah[mi], bh);
                    mma_bf16(acc[mi][nj], ah[mi], bl);
                    mma_bf16(acc[mi][nj], al[mi], bh);
                }
            }
        }
    }

    // ---- epilogue ----
    #pragma unroll
    for (int mi = 0; mi < 4; mi++) {
        int r0 = m0 + wm * 64 + mi * 16 + (int)(lane >> 2);
        #pragma unroll
        for (int nj = 0; nj < 4; nj++) {
            int col = n0 + wn * 32 + nj * 8 + (int)(lane & 3) * 2;
            float v[4];
            #pragma unroll
            for (int q = 0; q < 4; q++) v[q] = acc[mi][nj][q];
            if (EPI == 1 || EPI == 2) {
                float2 bb = *(const float2*)(bias + col);
                v[0] += bb.x; v[1] += bb.y; v[2] += bb.x; v[3] += bb.y;
            }
            if (EPI == 1) {
                float2 ra = *(const float2*)(res + (size_t)r0 * N + col);
                float2 rb = *(const float2*)(res + (size_t)(r0 + 8) * N + col);
                v[0] += ra.x; v[1] += ra.y; v[2] += rb.x; v[3] += rb.y;
            }
            if (EPI == 2) {
                #pragma unroll
                for (int q = 0; q < 4; q++)
                    v[q] = 0.5f * v[q] * (1.0f + erff(v[q] * 0.7071067811865476f));
            }
            if (EPI == 1) {
                float2 o0; o0.x = v[0]; o0.y = v[1];
                float2 o1; o1.x = v[2]; o1.y = v[3];
                *(float2*)(C + (size_t)r0 * N + col) = o0;
                *(float2*)(C + (size_t)(r0 + 8) * N + col) = o1;
            } else {
                float h0 = bf_hi(v[0]), h1 = bf_hi(v[1]);
                float h2 = bf_hi(v[2]), h3 = bf_hi(v[3]);
                *(uint32_t*)(Chi + (size_t)r0 * N + col)       = pack_hi2(h0, h1);
                *(uint32_t*)(Chi + (size_t)(r0 + 8) * N + col) = pack_hi2(h2, h3);
                *(uint32_t*)(Clo + (size_t)r0 * N + col)       = pack_hi2(v[0] - h0, v[1] - h1);
                *(uint32_t*)(Clo + (size_t)(r0 + 8) * N + col) = pack_hi2(v[2] - h2, v[3] - h3);
            }
        }
    }
}

// ================= tensor-core L2Q attention =================
// Block: 128 queries x one (b,h). 8 warps, each 16 query rows.
// S = Q@K^T (bf16x3), f = relu(a's^2+b's+g), rowsum; O += f@V (bf16x3, ldmatrix.trans).
#define AROW 144
#define A_QH 0
#define A_QL 18432
#define A_KH 36864
#define A_KL 46080
#define A_VH 55296
#define A_VL 64512
#define ATTN_SMEM 73728

__global__ __launch_bounds__(256) void attn_mma(const u16* __restrict__ qh,
                                                const u16* __restrict__ ql,
                                                const float* __restrict__ alpha,
                                                const float* __restrict__ beta,
                                                const float* __restrict__ gamma,
                                                u16* __restrict__ ohi,
                                                u16* __restrict__ olo)
{
    extern __shared__ char sm[];
    uint32_t sb = smem_u32(sm);
    int tid = threadIdx.x;
    int wid = tid >> 5;
    uint32_t lane = tid & 31;
    int bh = blockIdx.y;
    int b = bh / NH, h = bh % NH;
    int q0 = blockIdx.x * 128;
    float al2 = alpha[h] * 0.015625f;   // * SCALE^2
    float be2 = beta[h] * 0.125f;       // * SCALE
    float ga = gamma[h];

    size_t rowbase = (size_t)b * SEQ * QKVW;

    // ---- stage Q tile (128 x 64, hi+lo) ----
    #pragma unroll
    for (int p = 0; p < 8; p++) {
        const u16* src = (p < 4) ? qh : ql;
        int soff = (p < 4) ? A_QH : A_QL;
        int i = tid + (p & 3) * 256;          // 0..1023
        int r = i >> 3, q = i & 7;
        uint4 v = *(const uint4*)(src + rowbase + (size_t)(q0 + r) * QKVW + h * HD + q * 8);
        *(uint4*)(sm + soff + r * AROW + q * 16) = v;
    }
    __syncthreads();

    // ---- Q fragments (held in registers across all chunks) ----
    uint32_t aOffQ = (uint32_t)(wid * 16 + (lane & 15)) * AROW + (lane >> 4) * 16;
    uint32_t ah[4][4], al[4][4];
    #pragma unroll
    for (int ks = 0; ks < 4; ks++) {
        ldm_x4(ah[ks], sb + A_QH + aOffQ + ks * 32);
        ldm_x4(al[ks], sb + A_QL + aOffQ + ks * 32);
    }

    float o[8][4];
    #pragma unroll
    for (int d = 0; d < 8; d++)
        #pragma unroll
        for (int q = 0; q < 4; q++) o[d][q] = 0.f;
    float rs0 = 0.f, rs1 = 0.f;

    uint32_t kb = (uint32_t)((lane & 7) + ((lane >> 4) << 3)) * AROW + ((lane >> 3) & 1) * 16;
    uint32_t vb = (uint32_t)((lane & 7) + (((lane >> 3) & 1) << 3)) * AROW + (lane >> 4) * 16;

    for (int c = 0; c < SEQ / 64; c++) {
        __syncthreads();
        // ---- stage K,V tiles (64 x 64 each, hi+lo) ----
        #pragma unroll
        for (int p = 0; p < 8; p++) {
            int t = p >> 1;
            const u16* src = (t & 1) ? ql : qh;
            int coloff = (t < 2) ? (DIMC + h * HD) : (2 * DIMC + h * HD);
            int soff = (t == 0) ? A_KH : (t == 1) ? A_KL : (t == 2) ? A_VH : A_VL;
            int i = tid + (p & 1) * 256;      // 0..511
            int r = i >> 3, q = i & 7;
            uint4 v = *(const uint4*)(src + rowbase + (size_t)(c * 64 + r) * QKVW + coloff + q * 8);
            *(uint4*)(sm + soff + r * AROW + q * 16) = v;
        }
        __syncthreads();

        // ---- S = Q @ K^T ----
        float s[8][4];
        #pragma unroll
        for (int nf = 0; nf < 8; nf++)
            #pragma unroll
            for (int q = 0; q < 4; q++) s[nf][q] = 0.f;
        #pragma unroll
        for (int ks = 0; ks < 4; ks++) {
            uint32_t khf[4][4], klf[4][4];
            #pragma unroll
            for (int g = 0; g < 4; g++) {
                uint32_t ad = sb + kb + g * (16 * AROW) + ks * 32;
                ldm_x4(khf[g], ad + A_KH);
                ldm_x4(klf[g], ad + A_KL);
            }
            #pragma unroll
            for (int nf = 0; nf < 8; nf++) {
                const uint32_t* bhp = &khf[nf >> 1][(nf & 1) * 2];
                const uint32_t* blp = &klf[nf >> 1][(nf & 1) * 2];
                mma_bf16(s[nf], ah[ks], bhp);
                mma_bf16(s[nf], ah[ks], blp);
                mma_bf16(s[nf], al[ks], bhp);
            }
        }
        // ---- activation + rowsum ----
        #pragma unroll
        for (int nf = 0; nf < 8; nf++) {
            #pragma unroll
            for (int q = 0; q < 4; q++) {
                float xv = s[nf][q];
                float f = fmaf(al2 * xv, xv, fmaf(be2, xv, ga));
                f = fmaxf(f, 0.f);
                s[nf][q] = f;
                if (q < 2) rs0 += f; else rs1 += f;
            }
        }
        // ---- O += P @ V ----
        #pragma unroll
        for (int ks = 0; ks < 4; ks++) {
            float p00 = s[2 * ks][0], p01 = s[2 * ks][1], p02 = s[2 * ks][2], p03 = s[2 * ks][3];
            float p10 = s[2 * ks + 1][0], p11 = s[2 * ks + 1][1], p12 = s[2 * ks + 1][2], p13 = s[2 * ks + 1][3];
            float h00 = bf_hi(p00), h01 = bf_hi(p01), h02 = bf_hi(p02), h03 = bf_hi(p03);
            float h10 = bf_hi(p10), h11 = bf_hi(p11), h12 = bf_hi(p12), h13 = bf_hi(p13);
            uint32_t ph[4], pl[4];
            ph[0] = pack_hi2(h00, h01); ph[1] = pack_hi2(h02, h03);
            ph[2] = pack_hi2(h10, h11); ph[3] = pack_hi2(h12, h13);
            pl[0] = pack_hi2(p00 - h00, p01 - h01); pl[1] = pack_hi2(p02 - h02, p03 - h03);
            pl[2] = pack_hi2(p10 - h10, p11 - h11); pl[3] = pack_hi2(p12 - h12, p13 - h13);

            uint32_t vhf[4][4], vlf[4][4];
            #pragma unroll
            for (int g = 0; g < 4; g++) {
                uint32_t ad = sb + vb + ks * (16 * AROW) + g * 32;
                ldm_x4_t(vhf[g], ad + A_VH);
                ldm_x4_t(vlf[g], ad + A_VL);
            }
            #pragma unroll
            for (int df = 0; df < 8; df++) {
                const uint32_t* bhp = &vhf[df >> 1][(df & 1) * 2];
                const uint32_t* blp = &vlf[df >> 1][(df & 1) * 2];
                mma_bf16(o[df], ph, bhp);
                mma_bf16(o[df], ph, blp);
                mma_bf16(o[df], pl, bhp);
            }
        }
    }

    // ---- rowsum reduce over quad lanes ----
    rs0 += __shfl_xor_sync(0xFFFFFFFF, rs0, 1);
    rs0 += __shfl_xor_sync(0xFFFFFFFF, rs0, 2);
    rs1 += __shfl_xor_sync(0xFFFFFFFF, rs1, 1);
    rs1 += __shfl_xor_sync(0xFFFFFFFF, rs1, 2);
    float inv0 = 1.0f / (rs0 + 1e-6f);
    float inv1 = 1.0f / (rs1 + 1e-6f);

    // ---- write normalized O as bf16 hi/lo ----
    int grow = b * SEQ + q0 + wid * 16 + (int)(lane >> 2);
    #pragma unroll
    for (int df = 0; df < 8; df++) {
        int col = h * HD + df * 8 + (int)(lane & 3) * 2;
        float v0 = o[df][0] * inv0, v1 = o[df][1] * inv0;
        float v2 = o[df][2] * inv1, v3 = o[df][3] * inv1;
        float h0 = bf_hi(v0), h1 = bf_hi(v1), h2 = bf_hi(v2), h3 = bf_hi(v3);
        *(uint32_t*)(ohi + (size_t)grow * DIMC + col)       = pack_hi2(h0, h1);
        *(uint32_t*)(ohi + (size_t)(grow + 8) * DIMC + col) = pack_hi2(h2, h3);
        *(uint32_t*)(olo + (size_t)grow * DIMC + col)       = pack_hi2(v0 - h0, v1 - h1);
        *(uint32_t*)(olo + (size_t)(grow + 8) * DIMC + col) = pack_hi2(v2 - h2, v3 - h3);
    }
}

// ---------------- launch ------------------------------------------------------
extern "C" void kernel_launch(void* const* d_in, const int* in_sizes, int n_in,
                              void* d_out, int out_size)
{
    const float* x      = (const float*)d_in[0];
    const float* qkv_w  = (const float*)d_in[1];
    const float* proj_w = (const float*)d_in[2];
    const float* proj_b = (const float*)d_in[3];
    const float* alpha  = (const float*)d_in[4];
    const float* beta   = (const float*)d_in[5];
    const float* gamma  = (const float*)d_in[6];
    const float* ln1_w  = (const float*)d_in[7];
    const float* ln1_b  = (const float*)d_in[8];
    const float* ln2_w  = (const float*)d_in[9];
    const float* ln2_b  = (const float*)d_in[10];
    const float* w1     = (const float*)d_in[11];
    const float* b1     = (const float*)d_in[12];
    const float* w2     = (const float*)d_in[13];
    const float* b2     = (const float*)d_in[14];
    float* out = (float*)d_out;

    u16 *hh, *hl, *qvh, *qvl, *ath, *atl, *mph, *mpl;
    u16 *qwh, *qwl, *pwh, *pwl, *w1h, *w1l, *w2h, *w2l;
    cudaGetSymbolAddress((void**)&hh,  g_h_hi);   cudaGetSymbolAddress((void**)&hl,  g_h_lo);
    cudaGetSymbolAddress((void**)&qvh, g_qkv_hi); cudaGetSymbolAddress((void**)&qvl, g_qkv_lo);
    cudaGetSymbolAddress((void**)&ath, g_at_hi);  cudaGetSymbolAddress((void**)&atl, g_at_lo);
    cudaGetSymbolAddress((void**)&mph, g_mlp_hi); cudaGetSymbolAddress((void**)&mpl, g_mlp_lo);
    cudaGetSymbolAddress((void**)&qwh, g_qw_hi);  cudaGetSymbolAddress((void**)&qwl, g_qw_lo);
    cudaGetSymbolAddress((void**)&pwh, g_pw_hi);  cudaGetSymbolAddress((void**)&pwl, g_pw_lo);
    cudaGetSymbolAddress((void**)&w1h, g_w1_hi);  cudaGetSymbolAddress((void**)&w1l, g_w1_lo);
    cudaGetSymbolAddress((void**)&w2h, g_w2_hi);  cudaGetSymbolAddress((void**)&w2l, g_w2_lo);

    cudaFuncSetAttribute(attn_mma, cudaFuncAttributeMaxDynamicSharedMemorySize, ATTN_SMEM);

    // 0) split weights
    split_kernel<<<(QKVW * DIMC) / 1024, 256>>>(qkv_w, qwh, qwl);
    split_kernel<<<(DIMC * DIMC) / 1024, 256>>>(proj_w, pwh, pwl);
    split_kernel<<<(MLPD * DIMC) / 1024, 256>>>(w1, w1h, w1l);
    split_kernel<<<(DIMC * MLPD) / 1024, 256>>>(w2, w2h, w2l);
    // 1) LN1 -> bf16 hi/lo
    ln_kernel<<<ROWS, 128>>>(x, ln1_w, ln1_b, hh, hl);
    // 2) QKV gemm -> bf16 hi/lo
    mma_gemm<0><<<dim3(QKVW / 128, ROWS / 128), 256>>>(
        hh, hl, qwh, qwl, nullptr, nullptr, nullptr, qvh, qvl, ROWS, QKVW, DIMC);
    // 3) attention -> bf16 hi/lo
    attn_mma<<<dim3(SEQ / 128, BH), 256, ATTN_SMEM>>>(qvh, qvl, alpha, beta, gamma, ath, atl);
    // 4) proj + bias + residual(x) -> out fp32
    mma_gemm<1><<<dim3(DIMC / 128, ROWS / 128), 256>>>(
        ath, atl, pwh, pwl, proj_b, x, out, nullptr, nullptr, ROWS, DIMC, DIMC);
    // 5) LN2 -> bf16 hi/lo
    ln_kernel<<<ROWS, 128>>>(out, ln2_w, ln2_b, hh, hl);
    // 6) MLP1 + bias + GELU -> bf16 hi/lo
    mma_gemm<2><<<dim3(MLPD / 128, ROWS / 128), 256>>>(
        hh, hl, w1h, w1l, b1, nullptr, nullptr, mph, mpl, ROWS, MLPD, DIMC);
    // 7) MLP2 + bias + residual(out) -> out fp32
    mma_gemm<1><<<dim3(DIMC / 128, ROWS / 128), 256>>>(
        mph, mpl, w2h, w2l, b2, out, out, nullptr, nullptr, ROWS, DIMC, MLPD);
}

// round 7
// speedup vs baseline: 3.1776x; 1.4285x over previous
#include <cuda_runtime.h>
#include <cuda_fp16.h>
#include <math.h>
#include <stdint.h>

#define DIMC 384
#define NH 6
#define HD 64
#define MLPD 1536
#define BATCH 8
#define SEQ 1024
#define ROWS (BATCH*SEQ)   /* 8192 */
#define BH (BATCH*NH)      /* 48 */
#define QKVW (3*DIMC)      /* 1152 */

typedef unsigned short u16;

// ---------------- scratch (fp16; activations hi/lo, weights hi only) ----------
__device__ u16 g_h_hi[ROWS*DIMC],   g_h_lo[ROWS*DIMC];      // LN out
__device__ u16 g_qkv_hi[ROWS*QKVW], g_qkv_lo[ROWS*QKVW];    // QKV out
__device__ u16 g_at_hi[ROWS*DIMC],  g_at_lo[ROWS*DIMC];     // attn out
__device__ u16 g_mlp_hi[ROWS*MLPD], g_mlp_lo[ROWS*MLPD];    // MLP hidden
__device__ u16 g_qw[QKVW*DIMC];
__device__ u16 g_pw[DIMC*DIMC];
__device__ u16 g_w1[MLPD*DIMC];
__device__ u16 g_w2[DIMC*MLPD];

__device__ __forceinline__ uint32_t smem_u32(const void* p) {
    uint32_t a;
    asm("{ .reg .u64 t; cvta.to.shared.u64 t, %1; cvt.u32.u64 %0, t; }" : "=r"(a) : "l"(p));
    return a;
}
__device__ __forceinline__ void ldm_x4(uint32_t* r, uint32_t addr) {
    asm volatile("ldmatrix.sync.aligned.m8n8.x4.shared.b16 {%0,%1,%2,%3}, [%4];"
                 : "=r"(r[0]), "=r"(r[1]), "=r"(r[2]), "=r"(r[3]) : "r"(addr));
}
__device__ __forceinline__ void ldm_x4_t(uint32_t* r, uint32_t addr) {
    asm volatile("ldmatrix.sync.aligned.m8n8.x4.trans.shared.b16 {%0,%1,%2,%3}, [%4];"
                 : "=r"(r[0]), "=r"(r[1]), "=r"(r[2]), "=r"(r[3]) : "r"(addr));
}
__device__ __forceinline__ void mma_f16(float* d, const uint32_t* a, const uint32_t* b) {
    asm volatile("mma.sync.aligned.m16n8k16.row.col.f32.f16.f16.f32 "
                 "{%0,%1,%2,%3}, {%4,%5,%6,%7}, {%8,%9}, {%0,%1,%2,%3};"
                 : "+f"(d[0]), "+f"(d[1]), "+f"(d[2]), "+f"(d[3])
                 : "r"(a[0]), "r"(a[1]), "r"(a[2]), "r"(a[3]), "r"(b[0]), "r"(b[1]));
}
__device__ __forceinline__ float f16_hi(float x) {
    return __half2float(__float2half_rn(x));
}
__device__ __forceinline__ uint32_t packh2(float x, float y) {
    __half2 t = __floats2half2_rn(x, y);
    return *(uint32_t*)&t;
}
__device__ __forceinline__ u16 h_as_u16(float x) {
    __half t = __float2half_rn(x);
    return *(u16*)&t;
}

// ---------------- weight convert: fp32 -> fp16 ----------------
__global__ __launch_bounds__(256) void cvt_kernel(const float* __restrict__ in,
                                                  u16* __restrict__ hi)
{
    int idx = (blockIdx.x * 256 + threadIdx.x) * 4;
    float4 v = *(const float4*)(in + idx);
    uint2 a;
    a.x = packh2(v.x, v.y); a.y = packh2(v.z, v.w);
    *(uint2*)(hi + idx) = a;
}

// ---------------- LayerNorm -> fp16 hi/lo ----------------
__global__ __launch_bounds__(128) void ln_kernel(const float* __restrict__ x,
                                                 const float* __restrict__ w,
                                                 const float* __restrict__ b,
                                                 u16* __restrict__ ohi,
                                                 u16* __restrict__ olo)
{
    int row = blockIdx.x;
    const float* xr = x + (size_t)row * DIMC;
    int t = threadIdx.x;
    float v0 = xr[t], v1 = xr[t + 128], v2 = xr[t + 256];
    __shared__ float red[128];
    red[t] = v0 + v1 + v2;
    __syncthreads();
    #pragma unroll
    for (int o = 64; o > 0; o >>= 1) {
        if (t < o) red[t] += red[t + o];
        __syncthreads();
    }
    float mean = red[0] * (1.0f / DIMC);
    __syncthreads();
    float d0 = v0 - mean, d1 = v1 - mean, d2 = v2 - mean;
    red[t] = d0 * d0 + d1 * d1 + d2 * d2;
    __syncthreads();
    #pragma unroll
    for (int o = 64; o > 0; o >>= 1) {
        if (t < o) red[t] += red[t + o];
        __syncthreads();
    }
    float var = red[0] * (1.0f / DIMC);
    float r = rsqrtf(var + 1e-5f);
    size_t base = (size_t)row * DIMC;
    #pragma unroll
    for (int p = 0; p < 3; p++) {
        int i = t + p * 128;
        float d = (p == 0 ? d0 : p == 1 ? d1 : d2);
        float y = d * r * w[i] + b[i];
        float h = f16_hi(y);
        ohi[base + i] = h_as_u16(h);
        olo[base + i] = h_as_u16(y - h);
    }
}

// ================= mma.sync fp16x2 GEMM =================
// C[M,N] = A[M,K] @ W[N,K]^T,  acc += Ah*W + Al*W  (W single-rounded fp16).
// 256 threads (8 warps 2x4), tile TM x 128, K-chunk 32.
// EPI 0: split-store fp16 hi/lo   EPI 1: +bias +res -> fp32   EPI 2: +bias, GELU, split-store
#define LDS_ROW 80

template<int TM, int EPI>
__global__ __launch_bounds__(256) void mma_gemm(const u16* __restrict__ Ah_,
                                                const u16* __restrict__ Al_,
                                                const u16* __restrict__ Wh_,
                                                const float* __restrict__ bias,
                                                const float* __restrict__ res,
                                                float* __restrict__ C,
                                                u16* __restrict__ Chi,
                                                u16* __restrict__ Clo,
                                                int M, int N, int K)
{
    constexpr int MI = TM / 32;             // m16 frags per warp
    constexpr int ABYTES = TM * LDS_ROW;    // one A buffer
    constexpr int NPF = (TM == 128) ? 6 : 4;
    __shared__ __align__(128) char smem[2 * ABYTES + 128 * LDS_ROW];
    uint32_t sbase = smem_u32(smem);

    int tid = threadIdx.x;
    int wid = tid >> 5;
    uint32_t lane = tid & 31;
    int wm = wid >> 2, wn = wid & 3;
    int n0 = blockIdx.x * 128, m0 = blockIdx.y * TM;

    float acc[MI][4][4];
    #pragma unroll
    for (int i = 0; i < MI; i++)
        #pragma unroll
        for (int j = 0; j < 4; j++)
            #pragma unroll
            for (int q = 0; q < 4; q++) acc[i][j][q] = 0.f;

    uint32_t aOff = (uint32_t)(wm * (TM / 2) + (lane & 15)) * LDS_ROW + (lane >> 4) * 16;
    uint32_t bOff = 2 * ABYTES
                    + (uint32_t)(wn * 32 + (lane & 7) + ((lane >> 4) << 3)) * LDS_ROW
                    + ((lane >> 3) & 1) * 16;

    const u16* s0 = Ah_ + (size_t)m0 * K;
    const u16* s1 = Al_ + (size_t)m0 * K;
    const u16* s2 = Wh_ + (size_t)n0 * K;

    int nchunks = K >> 5;
    uint4 pf[NPF];

    auto ld_chunk = [&](int k0) {
        #pragma unroll
        for (int p = 0; p < NPF; p++) {
            int t, i;
            if (TM == 128) { t = p >> 1; i = tid + (p & 1) * 256; }
            else           { t = (p < 2) ? p : 2; i = (p < 2) ? tid : tid + (p - 2) * 256; }
            int r = i >> 2, q = i & 3;
            const u16* src = (t == 0) ? s0 : (t == 1) ? s1 : s2;
            pf[p] = *(const uint4*)(src + (size_t)r * K + k0 + q * 8);
        }
    };
    auto st_chunk = [&]() {
        #pragma unroll
        for (int p = 0; p < NPF; p++) {
            int t, i;
            if (TM == 128) { t = p >> 1; i = tid + (p & 1) * 256; }
            else           { t = (p < 2) ? p : 2; i = (p < 2) ? tid : tid + (p - 2) * 256; }
            int r = i >> 2, q = i & 3;
            int off = (t == 0) ? 0 : (t == 1) ? ABYTES : 2 * ABYTES;
            *(uint4*)(smem + off + r * LDS_ROW + q * 16) = pf[p];
        }
    };

    ld_chunk(0);
    for (int c = 0; c < nchunks; c++) {
        __syncthreads();
        st_chunk();
        __syncthreads();
        if (c + 1 < nchunks) ld_chunk((c + 1) << 5);

        #pragma unroll
        for (int ks = 0; ks < 2; ks++) {
            uint32_t ko = ks * 32;
            uint32_t ah[MI][4], al[MI][4], wh[2][4];
            #pragma unroll
            for (int mi = 0; mi < MI; mi++) {
                uint32_t ad = sbase + aOff + mi * (16 * LDS_ROW) + ko;
                ldm_x4(ah[mi], ad);
                ldm_x4(al[mi], ad + ABYTES);
            }
            #pragma unroll
            for (int j = 0; j < 2; j++)
                ldm_x4(wh[j], sbase + bOff + j * (16 * LDS_ROW) + ko);
            #pragma unroll
            for (int mi = 0; mi < MI; mi++) {
                #pragma unroll
                for (int nj = 0; nj < 4; nj++) {
                    const uint32_t* bp = &wh[nj >> 1][(nj & 1) * 2];
                    mma_f16(acc[mi][nj], ah[mi], bp);
                    mma_f16(acc[mi][nj], al[mi], bp);
                }
            }
        }
    }

    // ---- epilogue ----
    #pragma unroll
    for (int mi = 0; mi < MI; mi++) {
        int r0 = m0 + wm * (TM / 2) + mi * 16 + (int)(lane >> 2);
        #pragma unroll
        for (int nj = 0; nj < 4; nj++) {
            int col = n0 + wn * 32 + nj * 8 + (int)(lane & 3) * 2;
            float v[4];
            #pragma unroll
            for (int q = 0; q < 4; q++) v[q] = acc[mi][nj][q];
            if (EPI == 1 || EPI == 2) {
                float2 bb = *(const float2*)(bias + col);
                v[0] += bb.x; v[1] += bb.y; v[2] += bb.x; v[3] += bb.y;
            }
            if (EPI == 1) {
                float2 ra = *(const float2*)(res + (size_t)r0 * N + col);
                float2 rb = *(const float2*)(res + (size_t)(r0 + 8) * N + col);
                v[0] += ra.x; v[1] += ra.y; v[2] += rb.x; v[3] += rb.y;
            }
            if (EPI == 2) {
                #pragma unroll
                for (int q = 0; q < 4; q++)
                    v[q] = 0.5f * v[q] * (1.0f + erff(v[q] * 0.7071067811865476f));
            }
            if (EPI == 1) {
                float2 o0; o0.x = v[0]; o0.y = v[1];
                float2 o1; o1.x = v[2]; o1.y = v[3];
                *(float2*)(C + (size_t)r0 * N + col) = o0;
                *(float2*)(C + (size_t)(r0 + 8) * N + col) = o1;
            } else {
                float h0 = f16_hi(v[0]), h1 = f16_hi(v[1]);
                float h2 = f16_hi(v[2]), h3 = f16_hi(v[3]);
                *(uint32_t*)(Chi + (size_t)r0 * N + col)       = packh2(h0, h1);
                *(uint32_t*)(Chi + (size_t)(r0 + 8) * N + col) = packh2(h2, h3);
                *(uint32_t*)(Clo + (size_t)r0 * N + col)       = packh2(v[0] - h0, v[1] - h1);
                *(uint32_t*)(Clo + (size_t)(r0 + 8) * N + col) = packh2(v[2] - h2, v[3] - h3);
            }
        }
    }
}

// ================= tensor-core L2Q attention (fp16x2) =================
// 128 queries x one (b,h) per block, 8 warps x 16 query rows.
// S = (Qh+Ql)@K^T, f = relu(a's^2+b's+g), rowsum; O += (Ph+Pl)@V.  K,V single fp16.
#define AROW 144
#define A_QH 0
#define A_QL 18432
#define A_KH 36864
#define A_VH 46080
#define ATTN_SMEM 55296

__global__ __launch_bounds__(256) void attn_mma(const u16* __restrict__ qh,
                                                const u16* __restrict__ ql,
                                                const float* __restrict__ alpha,
                                                const float* __restrict__ beta,
                                                const float* __restrict__ gamma,
                                                u16* __restrict__ ohi,
                                                u16* __restrict__ olo)
{
    extern __shared__ char sm[];
    uint32_t sb = smem_u32(sm);
    int tid = threadIdx.x;
    int wid = tid >> 5;
    uint32_t lane = tid & 31;
    int bh = blockIdx.y;
    int b = bh / NH, h = bh % NH;
    int q0 = blockIdx.x * 128;
    float al2 = alpha[h] * 0.015625f;   // * SCALE^2
    float be2 = beta[h] * 0.125f;       // * SCALE
    float ga = gamma[h];

    size_t rowbase = (size_t)b * SEQ * QKVW;

    // ---- stage Q tile (128 x 64, hi+lo) ----
    #pragma unroll
    for (int p = 0; p < 8; p++) {
        const u16* src = (p < 4) ? qh : ql;
        int soff = (p < 4) ? A_QH : A_QL;
        int i = tid + (p & 3) * 256;
        int r = i >> 3, q = i & 7;
        uint4 v = *(const uint4*)(src + rowbase + (size_t)(q0 + r) * QKVW + h * HD + q * 8);
        *(uint4*)(sm + soff + r * AROW + q * 16) = v;
    }
    __syncthreads();

    uint32_t aOffQ = (uint32_t)(wid * 16 + (lane & 15)) * AROW + (lane >> 4) * 16;
    uint32_t ah[4][4], al[4][4];
    #pragma unroll
    for (int ks = 0; ks < 4; ks++) {
        ldm_x4(ah[ks], sb + A_QH + aOffQ + ks * 32);
        ldm_x4(al[ks], sb + A_QL + aOffQ + ks * 32);
    }

    float o[8][4];
    #pragma unroll
    for (int d = 0; d < 8; d++)
        #pragma unroll
        for (int q = 0; q < 4; q++) o[d][q] = 0.f;
    float rs0 = 0.f, rs1 = 0.f;

    uint32_t kb = (uint32_t)((lane & 7) + ((lane >> 4) << 3)) * AROW + ((lane >> 3) & 1) * 16;
    uint32_t vb = (uint32_t)((lane & 7) + (((lane >> 3) & 1) << 3)) * AROW + (lane >> 4) * 16;

    for (int c = 0; c < SEQ / 64; c++) {
        __syncthreads();
        // ---- stage K,V tiles (64 x 64, hi only) ----
        #pragma unroll
        for (int p = 0; p < 4; p++) {
            int t = p >> 1;
            int coloff = (t == 0) ? (DIMC + h * HD) : (2 * DIMC + h * HD);
            int soff = (t == 0) ? A_KH : A_VH;
            int i = tid + (p & 1) * 256;
            int r = i >> 3, q = i & 7;
            uint4 v = *(const uint4*)(qh + rowbase + (size_t)(c * 64 + r) * QKVW + coloff + q * 8);
            *(uint4*)(sm + soff + r * AROW + q * 16) = v;
        }
        __syncthreads();

        // ---- S = Q @ K^T ----
        float s[8][4];
        #pragma unroll
        for (int nf = 0; nf < 8; nf++)
            #pragma unroll
            for (int q = 0; q < 4; q++) s[nf][q] = 0.f;
        #pragma unroll
        for (int ks = 0; ks < 4; ks++) {
            uint32_t khf[4][4];
            #pragma unroll
            for (int g = 0; g < 4; g++)
                ldm_x4(khf[g], sb + A_KH + kb + g * (16 * AROW) + ks * 32);
            #pragma unroll
            for (int nf = 0; nf < 8; nf++) {
                const uint32_t* bp = &khf[nf >> 1][(nf & 1) * 2];
                mma_f16(s[nf], ah[ks], bp);
                mma_f16(s[nf], al[ks], bp);
            }
        }
        // ---- activation + rowsum ----
        #pragma unroll
        for (int nf = 0; nf < 8; nf++) {
            #pragma unroll
            for (int q = 0; q < 4; q++) {
                float xv = s[nf][q];
                float f = fmaf(al2 * xv, xv, fmaf(be2, xv, ga));
                f = fmaxf(f, 0.f);
                s[nf][q] = f;
                if (q < 2) rs0 += f; else rs1 += f;
            }
        }
        // ---- O += P @ V ----
        #pragma unroll
        for (int ks = 0; ks < 4; ks++) {
            float p00 = s[2 * ks][0], p01 = s[2 * ks][1], p02 = s[2 * ks][2], p03 = s[2 * ks][3];
            float p10 = s[2 * ks + 1][0], p11 = s[2 * ks + 1][1], p12 = s[2 * ks + 1][2], p13 = s[2 * ks + 1][3];
            float h00 = f16_hi(p00), h01 = f16_hi(p01), h02 = f16_hi(p02), h03 = f16_hi(p03);
            float h10 = f16_hi(p10), h11 = f16_hi(p11), h12 = f16_hi(p12), h13 = f16_hi(p13);
            uint32_t ph[4], pl[4];
            ph[0] = packh2(h00, h01); ph[1] = packh2(h02, h03);
            ph[2] = packh2(h10, h11); ph[3] = packh2(h12, h13);
            pl[0] = packh2(p00 - h00, p01 - h01); pl[1] = packh2(p02 - h02, p03 - h03);
            pl[2] = packh2(p10 - h10, p11 - h11); pl[3] = packh2(p12 - h12, p13 - h13);

            uint32_t vhf[4][4];
            #pragma unroll
            for (int g = 0; g < 4; g++)
                ldm_x4_t(vhf[g], sb + A_VH + vb + ks * (16 * AROW) + g * 32);
            #pragma unroll
            for (int df = 0; df < 8; df++) {
                const uint32_t* bp = &vhf[df >> 1][(df & 1) * 2];
                mma_f16(o[df], ph, bp);
                mma_f16(o[df], pl, bp);
            }
        }
    }

    // ---- rowsum reduce over quad lanes ----
    rs0 += __shfl_xor_sync(0xFFFFFFFF, rs0, 1);
    rs0 += __shfl_xor_sync(0xFFFFFFFF, rs0, 2);
    rs1 += __shfl_xor_sync(0xFFFFFFFF, rs1, 1);
    rs1 += __shfl_xor_sync(0xFFFFFFFF, rs1, 2);
    float inv0 = 1.0f / (rs0 + 1e-6f);
    float inv1 = 1.0f / (rs1 + 1e-6f);

    // ---- write normalized O as fp16 hi/lo ----
    int grow = b * SEQ + q0 + wid * 16 + (int)(lane >> 2);
    #pragma unroll
    for (int df = 0; df < 8; df++) {
        int col = h * HD + df * 8 + (int)(lane & 3) * 2;
        float v0 = o[df][0] * inv0, v1 = o[df][1] * inv0;
        float v2 = o[df][2] * inv1, v3 = o[df][3] * inv1;
        float h0 = f16_hi(v0), h1 = f16_hi(v1), h2 = f16_hi(v2), h3 = f16_hi(v3);
        *(uint32_t*)(ohi + (size_t)grow * DIMC + col)       = packh2(h0, h1);
        *(uint32_t*)(ohi + (size_t)(grow + 8) * DIMC + col) = packh2(h2, h3);
        *(uint32_t*)(olo + (size_t)grow * DIMC + col)       = packh2(v0 - h0, v1 - h1);
        *(uint32_t*)(olo + (size_t)(grow + 8) * DIMC + col) = packh2(v2 - h2, v3 - h3);
    }
}

// ---------------- launch ------------------------------------------------------
extern "C" void kernel_launch(void* const* d_in, const int* in_sizes, int n_in,
                              void* d_out, int out_size)
{
    const float* x      = (const float*)d_in[0];
    const float* qkv_w  = (const float*)d_in[1];
    const float* proj_w = (const float*)d_in[2];
    const float* proj_b = (const float*)d_in[3];
    const float* alpha  = (const float*)d_in[4];
    const float* beta   = (const float*)d_in[5];
    const float* gamma  = (const float*)d_in[6];
    const float* ln1_w  = (const float*)d_in[7];
    const float* ln1_b  = (const float*)d_in[8];
    const float* ln2_w  = (const float*)d_in[9];
    const float* ln2_b  = (const float*)d_in[10];
    const float* w1     = (const float*)d_in[11];
    const float* b1     = (const float*)d_in[12];
    const float* w2     = (const float*)d_in[13];
    const float* b2     = (const float*)d_in[14];
    float* out = (float*)d_out;

    u16 *hh, *hl, *qvh, *qvl, *ath, *atl, *mph, *mpl;
    u16 *qw, *pw, *w1h, *w2h;
    cudaGetSymbolAddress((void**)&hh,  g_h_hi);   cudaGetSymbolAddress((void**)&hl,  g_h_lo);
    cudaGetSymbolAddress((void**)&qvh, g_qkv_hi); cudaGetSymbolAddress((void**)&qvl, g_qkv_lo);
    cudaGetSymbolAddress((void**)&ath, g_at_hi);  cudaGetSymbolAddress((void**)&atl, g_at_lo);
    cudaGetSymbolAddress((void**)&mph, g_mlp_hi); cudaGetSymbolAddress((void**)&mpl, g_mlp_lo);
    cudaGetSymbolAddress((void**)&qw,  g_qw);
    cudaGetSymbolAddress((void**)&pw,  g_pw);
    cudaGetSymbolAddress((void**)&w1h, g_w1);
    cudaGetSymbolAddress((void**)&w2h, g_w2);

    cudaFuncSetAttribute(attn_mma, cudaFuncAttributeMaxDynamicSharedMemorySize, ATTN_SMEM);

    // 0) convert weights to fp16
    cvt_kernel<<<(QKVW * DIMC) / 1024, 256>>>(qkv_w, qw);
    cvt_kernel<<<(DIMC * DIMC) / 1024, 256>>>(proj_w, pw);
    cvt_kernel<<<(MLPD * DIMC) / 1024, 256>>>(w1, w1h);
    cvt_kernel<<<(DIMC * MLPD) / 1024, 256>>>(w2, w2h);
    // 1) LN1 -> fp16 hi/lo
    ln_kernel<<<ROWS, 128>>>(x, ln1_w, ln1_b, hh, hl);
    // 2) QKV gemm -> fp16 hi/lo
    mma_gemm<128, 0><<<dim3(QKVW / 128, ROWS / 128), 256>>>(
        hh, hl, qw, nullptr, nullptr, nullptr, qvh, qvl, ROWS, QKVW, DIMC);
    // 3) attention -> fp16 hi/lo
    attn_mma<<<dim3(SEQ / 128, BH), 256, ATTN_SMEM>>>(qvh, qvl, alpha, beta, gamma, ath, atl);
    // 4) proj + bias + residual(x) -> out fp32   (TM=64 for tail efficiency)
    mma_gemm<64, 1><<<dim3(DIMC / 128, ROWS / 64), 256>>>(
        ath, atl, pw, proj_b, x, out, nullptr, nullptr, ROWS, DIMC, DIMC);
    // 5) LN2 -> fp16 hi/lo
    ln_kernel<<<ROWS, 128>>>(out, ln2_w, ln2_b, hh, hl);
    // 6) MLP1 + bias + GELU -> fp16 hi/lo
    mma_gemm<128, 2><<<dim3(MLPD / 128, ROWS / 128), 256>>>(
        hh, hl, w1h, b1, nullptr, nullptr, mph, mpl, ROWS, MLPD, DIMC);
    // 7) MLP2 + bias + residual(out) -> out fp32  (TM=64)
    mma_gemm<64, 1><<<dim3(DIMC / 128, ROWS / 64), 256>>>(
        mph, mpl, w2h, b2, out, out, nullptr, nullptr, ROWS, DIMC, MLPD);
}

// round 8
// speedup vs baseline: 3.4768x; 1.0941x over previous
#include <cuda_runtime.h>
#include <cuda_fp16.h>
#include <math.h>
#include <stdint.h>

#define DIMC 384
#define NH 6
#define HD 64
#define MLPD 1536
#define BATCH 8
#define SEQ 1024
#define ROWS (BATCH*SEQ)   /* 8192 */
#define BH (BATCH*NH)      /* 48 */
#define QKVW (3*DIMC)      /* 1152 */

typedef unsigned short u16;

// ---------------- scratch (fp16; activations hi/lo, weights hi only) ----------
__device__ u16 g_h_hi[ROWS*DIMC],   g_h_lo[ROWS*DIMC];      // LN out
__device__ u16 g_qkv_hi[ROWS*QKVW], g_qkv_lo[ROWS*QKVW];    // QKV out
__device__ u16 g_at_hi[ROWS*DIMC],  g_at_lo[ROWS*DIMC];     // attn out
__device__ u16 g_mlp_hi[ROWS*MLPD], g_mlp_lo[ROWS*MLPD];    // MLP hidden
__device__ u16 g_qw[QKVW*DIMC];
__device__ u16 g_pw[DIMC*DIMC];
__device__ u16 g_w1[MLPD*DIMC];
__device__ u16 g_w2[DIMC*MLPD];

__device__ __forceinline__ uint32_t smem_u32(const void* p) {
    uint32_t a;
    asm("{ .reg .u64 t; cvta.to.shared.u64 t, %1; cvt.u32.u64 %0, t; }" : "=r"(a) : "l"(p));
    return a;
}
__device__ __forceinline__ void ldm_x4(uint32_t* r, uint32_t addr) {
    asm volatile("ldmatrix.sync.aligned.m8n8.x4.shared.b16 {%0,%1,%2,%3}, [%4];"
                 : "=r"(r[0]), "=r"(r[1]), "=r"(r[2]), "=r"(r[3]) : "r"(addr));
}
__device__ __forceinline__ void ldm_x4_t(uint32_t* r, uint32_t addr) {
    asm volatile("ldmatrix.sync.aligned.m8n8.x4.trans.shared.b16 {%0,%1,%2,%3}, [%4];"
                 : "=r"(r[0]), "=r"(r[1]), "=r"(r[2]), "=r"(r[3]) : "r"(addr));
}
__device__ __forceinline__ void mma_f16(float* d, const uint32_t* a, const uint32_t* b) {
    asm volatile("mma.sync.aligned.m16n8k16.row.col.f32.f16.f16.f32 "
                 "{%0,%1,%2,%3}, {%4,%5,%6,%7}, {%8,%9}, {%0,%1,%2,%3};"
                 : "+f"(d[0]), "+f"(d[1]), "+f"(d[2]), "+f"(d[3])
                 : "r"(a[0]), "r"(a[1]), "r"(a[2]), "r"(a[3]), "r"(b[0]), "r"(b[1]));
}
__device__ __forceinline__ float f16_hi(float x) {
    return __half2float(__float2half_rn(x));
}
__device__ __forceinline__ uint32_t packh2(float x, float y) {
    __half2 t = __floats2half2_rn(x, y);
    return *(uint32_t*)&t;
}
__device__ __forceinline__ u16 h_as_u16(float x) {
    __half t = __float2half_rn(x);
    return *(u16*)&t;
}

// ---------------- all-weights convert: fp32 -> fp16, one launch ----------------
#define CVT_B0 432   /* QKVW*DIMC/1024 */
#define CVT_B1 576   /* + DIMC*DIMC/1024 */
#define CVT_B2 1152  /* + MLPD*DIMC/1024 */
#define CVT_B3 1728  /* + DIMC*MLPD/1024 */
__global__ __launch_bounds__(256) void cvt_all(const float* __restrict__ s0,
                                               const float* __restrict__ s1,
                                               const float* __restrict__ s2,
                                               const float* __restrict__ s3,
                                               u16* d0, u16* d1, u16* d2, u16* d3)
{
    int blk = blockIdx.x;
    const float* src;
    u16* dst;
    int base;
    if (blk < CVT_B0)      { src = s0; dst = d0; base = 0; }
    else if (blk < CVT_B1) { src = s1; dst = d1; base = CVT_B0; }
    else if (blk < CVT_B2) { src = s2; dst = d2; base = CVT_B1; }
    else                   { src = s3; dst = d3; base = CVT_B2; }
    int idx = ((blk - base) * 256 + threadIdx.x) * 4;
    float4 v = *(const float4*)(src + idx);
    uint2 a;
    a.x = packh2(v.x, v.y); a.y = packh2(v.z, v.w);
    *(uint2*)(dst + idx) = a;
}

// ---------------- LayerNorm -> fp16 hi/lo (shuffle reduce) ----------------
__global__ __launch_bounds__(128) void ln_kernel(const float* __restrict__ x,
                                                 const float* __restrict__ w,
                                                 const float* __restrict__ b,
                                                 u16* __restrict__ ohi,
                                                 u16* __restrict__ olo)
{
    int row = blockIdx.x;
    const float* xr = x + (size_t)row * DIMC;
    int t = threadIdx.x;
    int lane = t & 31, wrp = t >> 5;
    float v0 = xr[t], v1 = xr[t + 128], v2 = xr[t + 256];
    __shared__ float ws[4];

    float sum = v0 + v1 + v2;
    #pragma unroll
    for (int o = 16; o > 0; o >>= 1) sum += __shfl_xor_sync(0xFFFFFFFF, sum, o);
    if (lane == 0) ws[wrp] = sum;
    __syncthreads();
    float mean = (ws[0] + ws[1] + ws[2] + ws[3]) * (1.0f / DIMC);

    float d0 = v0 - mean, d1 = v1 - mean, d2 = v2 - mean;
    float sq = d0 * d0 + d1 * d1 + d2 * d2;
    #pragma unroll
    for (int o = 16; o > 0; o >>= 1) sq += __shfl_xor_sync(0xFFFFFFFF, sq, o);
    __syncthreads();
    if (lane == 0) ws[wrp] = sq;
    __syncthreads();
    float var = (ws[0] + ws[1] + ws[2] + ws[3]) * (1.0f / DIMC);
    float r = rsqrtf(var + 1e-5f);

    size_t base = (size_t)row * DIMC;
    #pragma unroll
    for (int p = 0; p < 3; p++) {
        int i = t + p * 128;
        float d = (p == 0 ? d0 : p == 1 ? d1 : d2);
        float y = d * r * w[i] + b[i];
        float h = f16_hi(y);
        ohi[base + i] = h_as_u16(h);
        olo[base + i] = h_as_u16(y - h);
    }
}

// ================= mma.sync fp16x2 GEMM =================
// C[M,N] = A[M,K] @ W[N,K]^T,  acc += Ah*W + Al*W  (W single-rounded fp16).
// 256 threads (8 warps 2x4), tile TM x 128, K-chunk 32.
// EPI 0: split-store fp16 hi/lo   EPI 1: +bias +res -> fp32   EPI 2: +bias, GELU, split-store
#define LDS_ROW 80

template<int TM, int EPI>
__global__ __launch_bounds__(256) void mma_gemm(const u16* __restrict__ Ah_,
                                                const u16* __restrict__ Al_,
                                                const u16* __restrict__ Wh_,
                                                const float* __restrict__ bias,
                                                const float* __restrict__ res,
                                                float* __restrict__ C,
                                                u16* __restrict__ Chi,
                                                u16* __restrict__ Clo,
                                                int M, int N, int K)
{
    constexpr int MI = TM / 32;
    constexpr int ABYTES = TM * LDS_ROW;
    constexpr int NPF = (TM == 128) ? 6 : 4;
    __shared__ __align__(128) char smem[2 * ABYTES + 128 * LDS_ROW];
    uint32_t sbase = smem_u32(smem);

    int tid = threadIdx.x;
    int wid = tid >> 5;
    uint32_t lane = tid & 31;
    int wm = wid >> 2, wn = wid & 3;
    int n0 = blockIdx.x * 128, m0 = blockIdx.y * TM;

    float acc[MI][4][4];
    #pragma unroll
    for (int i = 0; i < MI; i++)
        #pragma unroll
        for (int j = 0; j < 4; j++)
            #pragma unroll
            for (int q = 0; q < 4; q++) acc[i][j][q] = 0.f;

    uint32_t aOff = (uint32_t)(wm * (TM / 2) + (lane & 15)) * LDS_ROW + (lane >> 4) * 16;
    uint32_t bOff = 2 * ABYTES
                    + (uint32_t)(wn * 32 + (lane & 7) + ((lane >> 4) << 3)) * LDS_ROW
                    + ((lane >> 3) & 1) * 16;

    const u16* s0 = Ah_ + (size_t)m0 * K;
    const u16* s1 = Al_ + (size_t)m0 * K;
    const u16* s2 = Wh_ + (size_t)n0 * K;

    int nchunks = K >> 5;
    uint4 pf[NPF];

    auto ld_chunk = [&](int k0) {
        #pragma unroll
        for (int p = 0; p < NPF; p++) {
            int t, i;
            if (TM == 128) { t = p >> 1; i = tid + (p & 1) * 256; }
            else           { t = (p < 2) ? p : 2; i = (p < 2) ? tid : tid + (p - 2) * 256; }
            int r = i >> 2, q = i & 3;
            const u16* src = (t == 0) ? s0 : (t == 1) ? s1 : s2;
            pf[p] = *(const uint4*)(src + (size_t)r * K + k0 + q * 8);
        }
    };
    auto st_chunk = [&]() {
        #pragma unroll
        for (int p = 0; p < NPF; p++) {
            int t, i;
            if (TM == 128) { t = p >> 1; i = tid + (p & 1) * 256; }
            else           { t = (p < 2) ? p : 2; i = (p < 2) ? tid : tid + (p - 2) * 256; }
            int r = i >> 2, q = i & 3;
            int off = (t == 0) ? 0 : (t == 1) ? ABYTES : 2 * ABYTES;
            *(uint4*)(smem + off + r * LDS_ROW + q * 16) = pf[p];
        }
    };

    ld_chunk(0);
    for (int c = 0; c < nchunks; c++) {
        __syncthreads();
        st_chunk();
        __syncthreads();
        if (c + 1 < nchunks) ld_chunk((c + 1) << 5);

        #pragma unroll
        for (int ks = 0; ks < 2; ks++) {
            uint32_t ko = ks * 32;
            uint32_t ah[MI][4], al[MI][4], wh[2][4];
            #pragma unroll
            for (int mi = 0; mi < MI; mi++) {
                uint32_t ad = sbase + aOff + mi * (16 * LDS_ROW) + ko;
                ldm_x4(ah[mi], ad);
                ldm_x4(al[mi], ad + ABYTES);
            }
            #pragma unroll
            for (int j = 0; j < 2; j++)
                ldm_x4(wh[j], sbase + bOff + j * (16 * LDS_ROW) + ko);
            #pragma unroll
            for (int mi = 0; mi < MI; mi++) {
                #pragma unroll
                for (int nj = 0; nj < 4; nj++) {
                    const uint32_t* bp = &wh[nj >> 1][(nj & 1) * 2];
                    mma_f16(acc[mi][nj], ah[mi], bp);
                    mma_f16(acc[mi][nj], al[mi], bp);
                }
            }
        }
    }

    // ---- epilogue ----
    #pragma unroll
    for (int mi = 0; mi < MI; mi++) {
        int r0 = m0 + wm * (TM / 2) + mi * 16 + (int)(lane >> 2);
        #pragma unroll
        for (int nj = 0; nj < 4; nj++) {
            int col = n0 + wn * 32 + nj * 8 + (int)(lane & 3) * 2;
            float v[4];
            #pragma unroll
            for (int q = 0; q < 4; q++) v[q] = acc[mi][nj][q];
            if (EPI == 1 || EPI == 2) {
                float2 bb = *(const float2*)(bias + col);
                v[0] += bb.x; v[1] += bb.y; v[2] += bb.x; v[3] += bb.y;
            }
            if (EPI == 1) {
                float2 ra = *(const float2*)(res + (size_t)r0 * N + col);
                float2 rb = *(const float2*)(res + (size_t)(r0 + 8) * N + col);
                v[0] += ra.x; v[1] += ra.y; v[2] += rb.x; v[3] += rb.y;
            }
            if (EPI == 2) {
                #pragma unroll
                for (int q = 0; q < 4; q++)
                    v[q] = 0.5f * v[q] * (1.0f + erff(v[q] * 0.7071067811865476f));
            }
            if (EPI == 1) {
                float2 o0; o0.x = v[0]; o0.y = v[1];
                float2 o1; o1.x = v[2]; o1.y = v[3];
                *(float2*)(C + (size_t)r0 * N + col) = o0;
                *(float2*)(C + (size_t)(r0 + 8) * N + col) = o1;
            } else {
                float h0 = f16_hi(v[0]), h1 = f16_hi(v[1]);
                float h2 = f16_hi(v[2]), h3 = f16_hi(v[3]);
                *(uint32_t*)(Chi + (size_t)r0 * N + col)       = packh2(h0, h1);
                *(uint32_t*)(Chi + (size_t)(r0 + 8) * N + col) = packh2(h2, h3);
                *(uint32_t*)(Clo + (size_t)r0 * N + col)       = packh2(v[0] - h0, v[1] - h1);
                *(uint32_t*)(Clo + (size_t)(r0 + 8) * N + col) = packh2(v[2] - h2, v[3] - h3);
            }
        }
    }
}

// ================= tensor-core L2Q attention (fp16) =================
// 128 queries x one (b,h) per block, 8 warps x 16 query rows.
// S = (Qh+Ql)@K^T, f = relu(a's^2+b's+g); P rounded to fp16, rowsum over ROUNDED P
// so O = sum(round(P) V)/sum(round(P)) is exactly normalized. K,V single fp16.
// K/V global loads register-prefetched one chunk ahead.
#define AROW 144
#define A_QH 0
#define A_QL 18432
#define A_KH 36864
#define A_VH 46080
#define ATTN_SMEM 55296

__global__ __launch_bounds__(256) void attn_mma(const u16* __restrict__ qh,
                                                const u16* __restrict__ ql,
                                                const float* __restrict__ alpha,
                                                const float* __restrict__ beta,
                                                const float* __restrict__ gamma,
                                                u16* __restrict__ ohi,
                                                u16* __restrict__ olo)
{
    extern __shared__ char sm[];
    uint32_t sb = smem_u32(sm);
    int tid = threadIdx.x;
    int wid = tid >> 5;
    uint32_t lane = tid & 31;
    int bh = blockIdx.y;
    int b = bh / NH, h = bh % NH;
    int q0 = blockIdx.x * 128;
    float al2 = alpha[h] * 0.015625f;   // * SCALE^2
    float be2 = beta[h] * 0.125f;       // * SCALE
    float ga = gamma[h];

    size_t rowbase = (size_t)b * SEQ * QKVW;

    // ---- stage Q tile (128 x 64, hi+lo) ----
    #pragma unroll
    for (int p = 0; p < 8; p++) {
        const u16* src = (p < 4) ? qh : ql;
        int soff = (p < 4) ? A_QH : A_QL;
        int i = tid + (p & 3) * 256;
        int r = i >> 3, q = i & 7;
        uint4 v = *(const uint4*)(src + rowbase + (size_t)(q0 + r) * QKVW + h * HD + q * 8);
        *(uint4*)(sm + soff + r * AROW + q * 16) = v;
    }
    __syncthreads();

    uint32_t aOffQ = (uint32_t)(wid * 16 + (lane & 15)) * AROW + (lane >> 4) * 16;
    uint32_t ah[4][4], al[4][4];
    #pragma unroll
    for (int ks = 0; ks < 4; ks++) {
        ldm_x4(ah[ks], sb + A_QH + aOffQ + ks * 32);
        ldm_x4(al[ks], sb + A_QL + aOffQ + ks * 32);
    }

    float o[8][4];
    #pragma unroll
    for (int d = 0; d < 8; d++)
        #pragma unroll
        for (int q = 0; q < 4; q++) o[d][q] = 0.f;
    float rs0 = 0.f, rs1 = 0.f;

    uint32_t kb = (uint32_t)((lane & 7) + ((lane >> 4) << 3)) * AROW + ((lane >> 3) & 1) * 16;
    uint32_t vb = (uint32_t)((lane & 7) + (((lane >> 3) & 1) << 3)) * AROW + (lane >> 4) * 16;

    // K/V chunk prefetch: 4 uint4 per thread (2 for K, 2 for V)
    uint4 pf[4];
    auto ld_kv = [&](int c) {
        #pragma unroll
        for (int p = 0; p < 4; p++) {
            int t = p >> 1;
            int coloff = (t == 0) ? (DIMC + h * HD) : (2 * DIMC + h * HD);
            int i = tid + (p & 1) * 256;
            int r = i >> 3, q = i & 7;
            pf[p] = *(const uint4*)(qh + rowbase + (size_t)(c * 64 + r) * QKVW + coloff + q * 8);
        }
    };
    auto st_kv = [&]() {
        #pragma unroll
        for (int p = 0; p < 4; p++) {
            int t = p >> 1;
            int soff = (t == 0) ? A_KH : A_VH;
            int i = tid + (p & 1) * 256;
            int r = i >> 3, q = i & 7;
            *(uint4*)(sm + soff + r * AROW + q * 16) = pf[p];
        }
    };

    ld_kv(0);
    for (int c = 0; c < SEQ / 64; c++) {
        __syncthreads();
        st_kv();
        __syncthreads();
        if (c + 1 < SEQ / 64) ld_kv(c + 1);

        // ---- S = Q @ K^T ----
        float s[8][4];
        #pragma unroll
        for (int nf = 0; nf < 8; nf++)
            #pragma unroll
            for (int q = 0; q < 4; q++) s[nf][q] = 0.f;
        #pragma unroll
        for (int ks = 0; ks < 4; ks++) {
            uint32_t khf[4][4];
            #pragma unroll
            for (int g = 0; g < 4; g++)
                ldm_x4(khf[g], sb + A_KH + kb + g * (16 * AROW) + ks * 32);
            #pragma unroll
            for (int nf = 0; nf < 8; nf++) {
                const uint32_t* bp = &khf[nf >> 1][(nf & 1) * 2];
                mma_f16(s[nf], ah[ks], bp);
                mma_f16(s[nf], al[ks], bp);
            }
        }
        // ---- activation ----
        #pragma unroll
        for (int nf = 0; nf < 8; nf++) {
            #pragma unroll
            for (int q = 0; q < 4; q++) {
                float xv = s[nf][q];
                float f = fmaf(al2 * xv, xv, fmaf(be2, xv, ga));
                s[nf][q] = fmaxf(f, 0.f);
            }
        }
        // ---- O += round(P) @ V ; rowsum over ROUNDED P ----
        #pragma unroll
        for (int ks = 0; ks < 4; ks++) {
            float h00 = f16_hi(s[2*ks][0]), h01 = f16_hi(s[2*ks][1]);
            float h02 = f16_hi(s[2*ks][2]), h03 = f16_hi(s[2*ks][3]);
            float h10 = f16_hi(s[2*ks+1][0]), h11 = f16_hi(s[2*ks+1][1]);
            float h12 = f16_hi(s[2*ks+1][2]), h13 = f16_hi(s[2*ks+1][3]);
            rs0 += h00 + h01 + h10 + h11;
            rs1 += h02 + h03 + h12 + h13;
            uint32_t ph[4];
            ph[0] = packh2(h00, h01); ph[1] = packh2(h02, h03);
            ph[2] = packh2(h10, h11); ph[3] = packh2(h12, h13);

            uint32_t vhf[4][4];
            #pragma unroll
            for (int g = 0; g < 4; g++)
                ldm_x4_t(vhf[g], sb + A_VH + vb + ks * (16 * AROW) + g * 32);
            #pragma unroll
            for (int df = 0; df < 8; df++)
                mma_f16(o[df], ph, &vhf[df >> 1][(df & 1) * 2]);
        }
    }

    // ---- rowsum reduce over quad lanes ----
    rs0 += __shfl_xor_sync(0xFFFFFFFF, rs0, 1);
    rs0 += __shfl_xor_sync(0xFFFFFFFF, rs0, 2);
    rs1 += __shfl_xor_sync(0xFFFFFFFF, rs1, 1);
    rs1 += __shfl_xor_sync(0xFFFFFFFF, rs1, 2);
    float inv0 = 1.0f / (rs0 + 1e-6f);
    float inv1 = 1.0f / (rs1 + 1e-6f);

    // ---- write normalized O as fp16 hi/lo ----
    int grow = b * SEQ + q0 + wid * 16 + (int)(lane >> 2);
    #pragma unroll
    for (int df = 0; df < 8; df++) {
        int col = h * HD + df * 8 + (int)(lane & 3) * 2;
        float v0 = o[df][0] * inv0, v1 = o[df][1] * inv0;
        float v2 = o[df][2] * inv1, v3 = o[df][3] * inv1;
        float h0 = f16_hi(v0), h1 = f16_hi(v1), h2 = f16_hi(v2), h3 = f16_hi(v3);
        *(uint32_t*)(ohi + (size_t)grow * DIMC + col)       = packh2(h0, h1);
        *(uint32_t*)(ohi + (size_t)(grow + 8) * DIMC + col) = packh2(h2, h3);
        *(uint32_t*)(olo + (size_t)grow * DIMC + col)       = packh2(v0 - h0, v1 - h1);
        *(uint32_t*)(olo + (size_t)(grow + 8) * DIMC + col) = packh2(v2 - h2, v3 - h3);
    }
}

// ---------------- launch ------------------------------------------------------
extern "C" void kernel_launch(void* const* d_in, const int* in_sizes, int n_in,
                              void* d_out, int out_size)
{
    const float* x      = (const float*)d_in[0];
    const float* qkv_w  = (const float*)d_in[1];
    const float* proj_w = (const float*)d_in[2];
    const float* proj_b = (const float*)d_in[3];
    const float* alpha  = (const float*)d_in[4];
    const float* beta   = (const float*)d_in[5];
    const float* gamma  = (const float*)d_in[6];
    const float* ln1_w  = (const float*)d_in[7];
    const float* ln1_b  = (const float*)d_in[8];
    const float* ln2_w  = (const float*)d_in[9];
    const float* ln2_b  = (const float*)d_in[10];
    const float* w1     = (const float*)d_in[11];
    const float* b1     = (const float*)d_in[12];
    const float* w2     = (const float*)d_in[13];
    const float* b2     = (const float*)d_in[14];
    float* out = (float*)d_out;

    u16 *hh, *hl, *qvh, *qvl, *ath, *atl, *mph, *mpl;
    u16 *qw, *pw, *w1h, *w2h;
    cudaGetSymbolAddress((void**)&hh,  g_h_hi);   cudaGetSymbolAddress((void**)&hl,  g_h_lo);
    cudaGetSymbolAddress((void**)&qvh, g_qkv_hi); cudaGetSymbolAddress((void**)&qvl, g_qkv_lo);
    cudaGetSymbolAddress((void**)&ath, g_at_hi);  cudaGetSymbolAddress((void**)&atl, g_at_lo);
    cudaGetSymbolAddress((void**)&mph, g_mlp_hi); cudaGetSymbolAddress((void**)&mpl, g_mlp_lo);
    cudaGetSymbolAddress((void**)&qw,  g_qw);
    cudaGetSymbolAddress((void**)&pw,  g_pw);
    cudaGetSymbolAddress((void**)&w1h, g_w1);
    cudaGetSymbolAddress((void**)&w2h, g_w2);

    cudaFuncSetAttribute(attn_mma, cudaFuncAttributeMaxDynamicSharedMemorySize, ATTN_SMEM);

    // 0) convert all weights to fp16 (one launch)
    cvt_all<<<CVT_B3, 256>>>(qkv_w, proj_w, w1, w2, qw, pw, w1h, w2h);
    // 1) LN1 -> fp16 hi/lo
    ln_kernel<<<ROWS, 128>>>(x, ln1_w, ln1_b, hh, hl);
    // 2) QKV gemm -> fp16 hi/lo
    mma_gemm<128, 0><<<dim3(QKVW / 128, ROWS / 128), 256>>>(
        hh, hl, qw, nullptr, nullptr, nullptr, qvh, qvl, ROWS, QKVW, DIMC);
    // 3) attention -> fp16 hi/lo
    attn_mma<<<dim3(SEQ / 128, BH), 256, ATTN_SMEM>>>(qvh, qvl, alpha, beta, gamma, ath, atl);
    // 4) proj + bias + residual(x) -> out fp32   (TM=64 for tail efficiency)
    mma_gemm<64, 1><<<dim3(DIMC / 128, ROWS / 64), 256>>>(
        ath, atl, pw, proj_b, x, out, nullptr, nullptr, ROWS, DIMC, DIMC);
    // 5) LN2 -> fp16 hi/lo
    ln_kernel<<<ROWS, 128>>>(out, ln2_w, ln2_b, hh, hl);
    // 6) MLP1 + bias + GELU -> fp16 hi/lo
    mma_gemm<128, 2><<<dim3(MLPD / 128, ROWS / 128), 256>>>(
        hh, hl, w1h, b1, nullptr, nullptr, mph, mpl, ROWS, MLPD, DIMC);
    // 7) MLP2 + bias + residual(out) -> out fp32  (TM=64)
    mma_gemm<64, 1><<<dim3(DIMC / 128, ROWS / 64), 256>>>(
        mph, mpl, w2h, b2, out, out, nullptr, nullptr, ROWS, DIMC, MLPD);
}